// round 1
// baseline (speedup 1.0000x reference)
#include <cuda_runtime.h>
#include <math.h>

#define BM 64
#define BK 16
#define EPS_VAR 1e-9f

#define SMAX (4*1472)

// ---------------- scratch (static device globals; no allocation) ----------------
__device__ float g_scores[(size_t)4*4096*4096];   // 256MB scores/attention buffer
__device__ float g_sum_q[SMAX], g_ss_q[SMAX], g_aq[SMAX], g_bq[SMAX];
__device__ float g_sum_k[SMAX], g_ss_k[SMAX], g_ak[SMAX], g_bk[SMAX];
__device__ float g_sum_c[SMAX], g_ss_c[SMAX], g_ac[SMAX], g_bc[SMAX];
__device__ double g_loss;

// ---------------- zero kernels ----------------
__global__ void zero_loss_kernel() { g_loss = 0.0; }

__global__ void zero_sums_kernel() {
    int i = blockIdx.x * blockDim.x + threadIdx.x;
    if (i < SMAX) {
        g_sum_q[i] = 0.f; g_ss_q[i] = 0.f;
        g_sum_k[i] = 0.f; g_ss_k[i] = 0.f;
        g_sum_c[i] = 0.f; g_ss_c[i] = 0.f;
    }
}

// ---------------- instance-norm stats ----------------
// T selects target arrays: 0 = q (comb_c), 1 = k (comb_s), 2 = c (content)
template<int T>
__global__ void stats_partial_t(const float* __restrict__ x, int N, int C, int rowsPerChunk) {
    float* gsum = (T == 0) ? g_sum_q : (T == 1) ? g_sum_k : g_sum_c;
    float* gss  = (T == 0) ? g_ss_q  : (T == 1) ? g_ss_k  : g_ss_c;
    int b = blockIdx.x, chunk = blockIdx.y;
    int r0 = chunk * rowsPerChunk;
    for (int c = threadIdx.x; c < C; c += blockDim.x) {
        float s = 0.f, ss = 0.f;
        const float* p = x + ((size_t)b * N + r0) * C + c;
        for (int r = 0; r < rowsPerChunk; r++) {
            float v = p[(size_t)r * C];
            s += v; ss = fmaf(v, v, ss);
        }
        atomicAdd(&gsum[b * C + c], s);
        atomicAdd(&gss[b * C + c], ss);
    }
}

template<int T>
__global__ void stats_final_t(int N, int C, int B) {
    const float* gsum = (T == 0) ? g_sum_q : (T == 1) ? g_sum_k : g_sum_c;
    const float* gss  = (T == 0) ? g_ss_q  : (T == 1) ? g_ss_k  : g_ss_c;
    float* ga = (T == 0) ? g_aq : (T == 1) ? g_ak : g_ac;
    float* gb = (T == 0) ? g_bq : (T == 1) ? g_bk : g_bc;
    int i = blockIdx.x * blockDim.x + threadIdx.x;
    if (i < B * C) {
        float invN = 1.0f / (float)N;
        float mean = gsum[i] * invN;
        float var  = gss[i] * invN - mean * mean;
        float r = rsqrtf(var + 1e-5f);
        ga[i] = r;
        gb[i] = -mean * r;
    }
}

// ---------------- scores = Qn * Kn^T  (N x N, K = Cc) ----------------
__global__ __launch_bounds__(256)
void gemm_qk(const float* __restrict__ q, const float* __restrict__ k,
             int N, int Cc) {
    __shared__ float As[BK][BM + 1];
    __shared__ float Bs[BK][BM + 1];
    int b = blockIdx.z;
    int bi = blockIdx.y * BM, bj = blockIdx.x * BM;
    int tid = threadIdx.x;
    int tx = tid & 15, ty = tid >> 4;

    const float* qb = q + (size_t)b * N * Cc;
    const float* kb = k + (size_t)b * N * Cc;
    const float* aqb = g_aq + b * Cc; const float* bqb = g_bq + b * Cc;
    const float* akb = g_ak + b * Cc; const float* bkb = g_bk + b * Cc;

    float acc[4][4] = {};

    for (int k0 = 0; k0 < Cc; k0 += BK) {
        #pragma unroll
        for (int p = 0; p < 4; p++) {
            int idx = tid + p * 256;
            int r = idx >> 4, cc = idx & 15;
            int ch = k0 + cc;
            float va = qb[(size_t)(bi + r) * Cc + ch];
            As[cc][r] = fmaf(va, aqb[ch], bqb[ch]);
            float vb = kb[(size_t)(bj + r) * Cc + ch];
            Bs[cc][r] = fmaf(vb, akb[ch], bkb[ch]);
        }
        __syncthreads();
        #pragma unroll
        for (int kk = 0; kk < BK; kk++) {
            float a4[4], b4[4];
            #pragma unroll
            for (int ii = 0; ii < 4; ii++) a4[ii] = As[kk][ty + ii * 16];
            #pragma unroll
            for (int jj = 0; jj < 4; jj++) b4[jj] = Bs[kk][tx + jj * 16];
            #pragma unroll
            for (int ii = 0; ii < 4; ii++)
                #pragma unroll
                for (int jj = 0; jj < 4; jj++)
                    acc[ii][jj] = fmaf(a4[ii], b4[jj], acc[ii][jj]);
        }
        __syncthreads();
    }

    float* sb = g_scores + (size_t)b * N * N;
    #pragma unroll
    for (int ii = 0; ii < 4; ii++) {
        int gi = bi + ty + ii * 16;
        #pragma unroll
        for (int jj = 0; jj < 4; jj++) {
            int gj = bj + tx + jj * 16;
            sb[(size_t)gi * N + gj] = acc[ii][jj];
        }
    }
}

// ---------------- row softmax in-place on g_scores ----------------
__global__ void softmax_rows(int N) {
    extern __shared__ float srow[];
    __shared__ float red[33];
    size_t row = blockIdx.x;
    float* p = g_scores + row * (size_t)N;
    int tid = threadIdx.x, bd = blockDim.x;

    float m = -1e30f;
    for (int j = tid; j < N; j += bd) {
        float v = p[j];
        srow[j] = v;
        m = fmaxf(m, v);
    }
    #pragma unroll
    for (int o = 16; o > 0; o >>= 1) m = fmaxf(m, __shfl_xor_sync(0xffffffffu, m, o));
    if ((tid & 31) == 0) red[tid >> 5] = m;
    __syncthreads();
    if (tid < 32) {
        float v = (tid < (bd >> 5)) ? red[tid] : -1e30f;
        #pragma unroll
        for (int o = 16; o > 0; o >>= 1) v = fmaxf(v, __shfl_xor_sync(0xffffffffu, v, o));
        if (tid == 0) red[32] = v;
    }
    __syncthreads();
    m = red[32];

    float s = 0.f;
    for (int j = tid; j < N; j += bd) {
        float e = expf(srow[j] - m);
        srow[j] = e;
        s += e;
    }
    __syncthreads();
    #pragma unroll
    for (int o = 16; o > 0; o >>= 1) s += __shfl_xor_sync(0xffffffffu, s, o);
    if ((tid & 31) == 0) red[tid >> 5] = s;
    __syncthreads();
    if (tid < 32) {
        float v = (tid < (bd >> 5)) ? red[tid] : 0.f;
        #pragma unroll
        for (int o = 16; o > 0; o >>= 1) v += __shfl_xor_sync(0xffffffffu, v, o);
        if (tid == 0) red[32] = v;
    }
    __syncthreads();
    float inv = 1.0f / red[32];
    for (int j = tid; j < N; j += bd) p[j] = srow[j] * inv;
}

// ---------------- M = A*V, T = A*V^2, then S, aat, squared-error ----------------
__global__ __launch_bounds__(256)
void gemm_av(const float* __restrict__ v, const float* __restrict__ cin,
             const float* __restrict__ cs, int N, int C, float inv_count) {
    __shared__ float As[BK][BM + 1];
    __shared__ float Vs[BK][BM];
    __shared__ float V2s[BK][BM];
    int b = blockIdx.z;
    int bi = blockIdx.y * BM, bc = blockIdx.x * BM;
    int tid = threadIdx.x;
    int tx = tid & 15, ty = tid >> 4;

    const float* Ab = g_scores + (size_t)b * N * N;
    const float* vb = v + (size_t)b * N * C;

    float accM[4][4] = {}, accT[4][4] = {};

    for (int j0 = 0; j0 < N; j0 += BK) {
        #pragma unroll
        for (int p = 0; p < 4; p++) {
            int idx = tid + p * 256;
            int r = idx >> 4, cc = idx & 15;
            As[cc][r] = Ab[(size_t)(bi + r) * N + j0 + cc];
            int r2 = idx >> 6, c2 = idx & 63;
            float val = vb[(size_t)(j0 + r2) * C + bc + c2];
            Vs[r2][c2] = val;
            V2s[r2][c2] = val * val;
        }
        __syncthreads();
        #pragma unroll
        for (int kk = 0; kk < BK; kk++) {
            float a4[4], b4[4], b24[4];
            #pragma unroll
            for (int ii = 0; ii < 4; ii++) a4[ii] = As[kk][ty + ii * 16];
            #pragma unroll
            for (int jj = 0; jj < 4; jj++) { b4[jj] = Vs[kk][tx + jj * 16]; b24[jj] = V2s[kk][tx + jj * 16]; }
            #pragma unroll
            for (int ii = 0; ii < 4; ii++)
                #pragma unroll
                for (int jj = 0; jj < 4; jj++) {
                    accM[ii][jj] = fmaf(a4[ii], b4[jj],  accM[ii][jj]);
                    accT[ii][jj] = fmaf(a4[ii], b24[jj], accT[ii][jj]);
                }
        }
        __syncthreads();
    }

    const float* acb = g_ac + b * C;
    const float* bcb = g_bc + b * C;
    float local = 0.f;
    #pragma unroll
    for (int ii = 0; ii < 4; ii++) {
        int gi = bi + ty + ii * 16;
        #pragma unroll
        for (int jj = 0; jj < 4; jj++) {
            int gc = bc + tx + jj * 16;
            size_t off = ((size_t)b * N + gi) * C + gc;
            float m = accM[ii][jj], t = accT[ii][jj];
            float s2 = t - m * m;
            float s = sqrtf(fmaxf(s2, EPS_VAR));
            float nc = fmaf(cin[off], acb[gc], bcb[gc]);
            float aat = fmaf(s, nc, m);
            float d = cs[off] - aat;
            local = fmaf(d, d, local);
        }
    }
    local *= inv_count;

    // block reduce
    #pragma unroll
    for (int o = 16; o > 0; o >>= 1) local += __shfl_xor_sync(0xffffffffu, local, o);
    __shared__ float red[8];
    if ((tid & 31) == 0) red[tid >> 5] = local;
    __syncthreads();
    if (tid == 0) {
        float t = 0.f;
        #pragma unroll
        for (int i = 0; i < 8; i++) t += red[i];
        atomicAdd(&g_loss, (double)t);
    }
}

__global__ void write_out_kernel(float* out) { out[0] = (float)g_loss; }

// ---------------- host launcher ----------------
extern "C" void kernel_launch(void* const* d_in, const int* in_sizes, int n_in,
                              void* d_out, int out_size) {
    (void)in_sizes; (void)n_in; (void)out_size;
    const int B = 4;
    struct P { int i_cs, i_c, i_s, i_cc, i_sc, N, C, Cc, chunks; };
    P ps[3] = {
        { 0, 1, 2, 3, 4, 4096, 256,  448, 64},
        { 5, 6, 7, 8, 9, 1024, 512,  960, 32},
        {10,11,12,13,14, 256, 512, 1472, 16},
    };

    zero_loss_kernel<<<1, 1>>>();

    for (int s = 0; s < 3; s++) {
        const P& p = ps[s];
        const float* cs = (const float*)d_in[p.i_cs];
        const float* c  = (const float*)d_in[p.i_c];
        const float* st = (const float*)d_in[p.i_s];
        const float* cc = (const float*)d_in[p.i_cc];
        const float* sc = (const float*)d_in[p.i_sc];

        zero_sums_kernel<<<(SMAX + 255) / 256, 256>>>();

        dim3 gs(B, p.chunks);
        int rows = p.N / p.chunks;
        stats_partial_t<0><<<gs, 256>>>(cc, p.N, p.Cc, rows);
        stats_partial_t<1><<<gs, 256>>>(sc, p.N, p.Cc, rows);
        stats_partial_t<2><<<gs, 256>>>(c,  p.N, p.C,  rows);

        stats_final_t<0><<<(B * p.Cc + 255) / 256, 256>>>(p.N, p.Cc, B);
        stats_final_t<1><<<(B * p.Cc + 255) / 256, 256>>>(p.N, p.Cc, B);
        stats_final_t<2><<<(B * p.C  + 255) / 256, 256>>>(p.N, p.C,  B);

        dim3 g1(p.N / BM, p.N / BM, B);
        gemm_qk<<<g1, 256>>>(cc, sc, p.N, p.Cc);

        softmax_rows<<<B * p.N, 256, p.N * sizeof(float)>>>(p.N);

        float inv_count = 1.0f / ((float)B * p.N * p.C);
        dim3 g2(p.C / BM, p.N / BM, B);
        gemm_av<<<g2, 256>>>(st, c, cs, p.N, p.C, inv_count);
    }

    write_out_kernel<<<1, 1>>>((float*)d_out);
}

// round 5
// speedup vs baseline: 2.2651x; 2.2651x over previous
#include <cuda_runtime.h>
#include <cuda_bf16.h>
#include <cstdint>
#include <math.h>

#define EPS_VAR 1e-9f
#define SMAX (4*1472)

// ---------------- scratch (static device globals; no allocation) ----------------
// NOTE: device globals are ONLY referenced from device code (never passed as
// kernel arguments from host — host would pass the host shadow address, which
// ATS happily dereferences into host BSS, silently splitting the pipeline).
__device__ float g_scores[(size_t)4*4096*4096];                  // 256MB fp32 scores
__device__ __nv_bfloat16 g_Ahi[(size_t)4*4096*4096];             // softmax probs hi
__device__ __nv_bfloat16 g_Alo[(size_t)4*4096*4096];             // softmax probs lo
__device__ __nv_bfloat16 g_Qhi[7340032], g_Qlo[7340032];
__device__ __nv_bfloat16 g_Khi[7340032], g_Klo[7340032];
__device__ __nv_bfloat16 g_Whi[8388608], g_Wlo[8388608];         // [V^T ; (V^2)^T]
__device__ float g_MT[8388608];                                  // [M | T] output
__device__ float g_sum_q[SMAX], g_ss_q[SMAX], g_aq[SMAX], g_bq[SMAX];
__device__ float g_sum_k[SMAX], g_ss_k[SMAX], g_ak[SMAX], g_bk[SMAX];
__device__ float g_sum_c[SMAX], g_ss_c[SMAX], g_ac[SMAX], g_bc[SMAX];
__device__ double g_loss;

// ---------------- PTX helpers (sm_80-level baseline features only) ----------------
__device__ __forceinline__ uint32_t smem_u32(const void* p){
    uint32_t a; asm("{ .reg .u64 t; cvta.to.shared.u64 t, %1; cvt.u32.u64 %0, t; }" : "=r"(a) : "l"(p)); return a;
}
__device__ __forceinline__ void cp_async16(uint32_t dst, const void* src){
    asm volatile("cp.async.cg.shared.global [%0], [%1], 16;" :: "r"(dst), "l"(src) : "memory");
}
#define CP_COMMIT() asm volatile("cp.async.commit_group;" ::: "memory")
#define CP_WAIT(n)  asm volatile("cp.async.wait_group %0;" :: "n"(n) : "memory")

__device__ __forceinline__ uint32_t lds32(uint32_t addr){
    uint32_t v; asm volatile("ld.shared.b32 %0, [%1];" : "=r"(v) : "r"(addr)); return v;
}
__device__ __forceinline__ void mma_bf16(float* c, const uint32_t* a, const uint32_t* b){
    asm volatile("mma.sync.aligned.m16n8k16.row.col.f32.bf16.bf16.f32 "
        "{%0,%1,%2,%3}, {%4,%5,%6,%7}, {%8,%9}, {%0,%1,%2,%3};"
        : "+f"(c[0]), "+f"(c[1]), "+f"(c[2]), "+f"(c[3])
        : "r"(a[0]), "r"(a[1]), "r"(a[2]), "r"(a[3]), "r"(b[0]), "r"(b[1]));
}

// ---------------- small kernels ----------------
__global__ void zero_loss_kernel() { g_loss = 0.0; }

__global__ void zero_sums_kernel() {
    int i = blockIdx.x * blockDim.x + threadIdx.x;
    if (i < SMAX) {
        g_sum_q[i] = 0.f; g_ss_q[i] = 0.f;
        g_sum_k[i] = 0.f; g_ss_k[i] = 0.f;
        g_sum_c[i] = 0.f; g_ss_c[i] = 0.f;
    }
}

template<int T>
__global__ void stats_partial_t(const float* __restrict__ x, int N, int C, int rowsPerChunk) {
    float* gsum = (T == 0) ? g_sum_q : (T == 1) ? g_sum_k : g_sum_c;
    float* gss  = (T == 0) ? g_ss_q  : (T == 1) ? g_ss_k  : g_ss_c;
    int b = blockIdx.x, chunk = blockIdx.y;
    int r0 = chunk * rowsPerChunk;
    for (int c = threadIdx.x; c < C; c += blockDim.x) {
        float s = 0.f, ss = 0.f;
        const float* p = x + ((size_t)b * N + r0) * C + c;
        for (int r = 0; r < rowsPerChunk; r++) {
            float v = p[(size_t)r * C];
            s += v; ss = fmaf(v, v, ss);
        }
        atomicAdd(&gsum[b * C + c], s);
        atomicAdd(&gss[b * C + c], ss);
    }
}

template<int T>
__global__ void stats_final_t(int N, int C, int B) {
    const float* gsum = (T == 0) ? g_sum_q : (T == 1) ? g_sum_k : g_sum_c;
    const float* gss  = (T == 0) ? g_ss_q  : (T == 1) ? g_ss_k  : g_ss_c;
    float* ga = (T == 0) ? g_aq : (T == 1) ? g_ak : g_ac;
    float* gb = (T == 0) ? g_bq : (T == 1) ? g_bk : g_bc;
    int i = blockIdx.x * blockDim.x + threadIdx.x;
    if (i < B * C) {
        float invN = 1.0f / (float)N;
        float mean = gsum[i] * invN;
        float var  = gss[i] * invN - mean * mean;
        float r = rsqrtf(var + 1e-5f);
        ga[i] = r;
        gb[i] = -mean * r;
    }
}

// normalize + split fp32 -> bf16 hi/lo.  T=0: comb_c -> Q;  T=1: comb_s -> K
template<int T>
__global__ void prep_split_affine(const float* __restrict__ x,
                                  int total, int C, int perBatch) {
    const float* ga = (T == 0) ? g_aq : g_ak;
    const float* gb = (T == 0) ? g_bq : g_bk;
    __nv_bfloat16* hi = (T == 0) ? g_Qhi : g_Khi;
    __nv_bfloat16* lo = (T == 0) ? g_Qlo : g_Klo;
    int i = blockIdx.x * blockDim.x + threadIdx.x;
    if (i >= total) return;
    int b = i / perBatch;
    int ch = i % C;
    float y = fmaf(x[i], ga[b * C + ch], gb[b * C + ch]);
    __nv_bfloat16 h = __float2bfloat16(y);
    hi[i] = h;
    lo[i] = __float2bfloat16(y - __bfloat162float(h));
}

// W = [V^T ; (V^2)^T]  (2C x N per batch), bf16 hi/lo
__global__ void prep_w(const float* __restrict__ v, int N, int C) {
    __shared__ float tile[32][33];
    int b = blockIdx.z;
    int j0 = blockIdx.x * 32, c0 = blockIdx.y * 32;
    int tx = threadIdx.x, ty = threadIdx.y;  // 32 x 8
    const float* vb = v + (size_t)b * N * C;
    #pragma unroll
    for (int r = 0; r < 4; r++)
        tile[ty + 8 * r][tx] = vb[(size_t)(j0 + ty + 8 * r) * C + c0 + tx];
    __syncthreads();
    size_t base = (size_t)b * 2 * C * N;
    #pragma unroll
    for (int r = 0; r < 4; r++) {
        int c = c0 + ty + 8 * r, j = j0 + tx;
        float val = tile[tx][ty + 8 * r];
        __nv_bfloat16 h = __float2bfloat16(val);
        g_Whi[base + (size_t)c * N + j] = h;
        g_Wlo[base + (size_t)c * N + j] = __float2bfloat16(val - __bfloat162float(h));
        float v2 = val * val;
        __nv_bfloat16 h2 = __float2bfloat16(v2);
        g_Whi[base + (size_t)(C + c) * N + j] = h2;
        g_Wlo[base + (size_t)(C + c) * N + j] = __float2bfloat16(v2 - __bfloat162float(h2));
    }
}

// ---------------- mma.sync split-bf16 GEMM: D = X * Y^T ----------------
// MODE 0: X = Qn (Mg=N, Kg=Cc), Y = Kn (Ng=N), D = g_scores
// MODE 1: X = A  (Mg=N, Kg=N),  Y = W  (Ng=2C), D = g_MT
// 128x128 block tile, 8 warps of 64x32, K-chunk 16, cp.async double buffered.
// smem tile: 128 rows x 16 cols bf16, stride 32B; 4 tiles/stage = 16KB; 2 stages.
#define KCH 16
#define TROWB 32
#define TILE_BYTES (128 * TROWB)
#define STAGE_BYTES (4 * TILE_BYTES)
#define GEMM_SMEM (2 * STAGE_BYTES)

__device__ __forceinline__ void load_chunk(uint32_t sbase,
        const __nv_bfloat16* xh, const __nv_bfloat16* xl,
        const __nv_bfloat16* yh, const __nv_bfloat16* yl,
        int Kg, int k0, int tid) {
    const __nv_bfloat16* srcs[4] = { xh, xl, yh, yl };
    #pragma unroll
    for (int a = 0; a < 4; a++) {
        int r = tid >> 1, h = tid & 1;      // 256 16B vectors: 128 rows x 2 halves
        cp_async16(sbase + a * TILE_BYTES + r * TROWB + h * 16,
                   srcs[a] + (size_t)r * Kg + k0 + h * 8);
    }
}

template<int MODE>
__global__ __launch_bounds__(256)
void gemm_bf16split(int Mg, int Ng, int Kg) {
    extern __shared__ char smem[];
    uint32_t sb = smem_u32(smem);
    int tid = threadIdx.x;
    int wid = tid >> 5, lane = tid & 31;
    int g = lane >> 2, t = lane & 3;
    int warp_m0 = (wid >> 2) << 6;   // 0 or 64
    int warp_n0 = (wid & 3) << 5;    // 0,32,64,96
    int b = blockIdx.z;
    int bi = blockIdx.y * 128, bj = blockIdx.x * 128;

    const __nv_bfloat16* Xhi = (MODE == 0) ? g_Qhi : g_Ahi;
    const __nv_bfloat16* Xlo = (MODE == 0) ? g_Qlo : g_Alo;
    const __nv_bfloat16* Yhi = (MODE == 0) ? g_Khi : g_Whi;
    const __nv_bfloat16* Ylo = (MODE == 0) ? g_Klo : g_Wlo;
    float* D = (MODE == 0) ? g_scores : g_MT;

    const __nv_bfloat16* xh = Xhi + (size_t)b * Mg * Kg + (size_t)bi * Kg;
    const __nv_bfloat16* xl = Xlo + (size_t)b * Mg * Kg + (size_t)bi * Kg;
    const __nv_bfloat16* yh = Yhi + (size_t)b * Ng * Kg + (size_t)bj * Kg;
    const __nv_bfloat16* yl = Ylo + (size_t)b * Ng * Kg + (size_t)bj * Kg;

    float acc[4][4][4];
    #pragma unroll
    for (int i = 0; i < 4; i++)
        #pragma unroll
        for (int j = 0; j < 4; j++)
            #pragma unroll
            for (int k = 0; k < 4; k++) acc[i][j][k] = 0.f;

    int nch = Kg / KCH;

    // per-lane byte offsets within a tile (PTX mma fragment spec, direct LDS)
    uint32_t aoff = (uint32_t)((warp_m0 + g) * TROWB + t * 4);
    uint32_t boff = (uint32_t)((warp_n0 + g) * TROWB + t * 4);

    load_chunk(sb, xh, xl, yh, yl, Kg, 0, tid);
    CP_COMMIT();

    for (int i = 0; i < nch; i++) {
        uint32_t stage = (uint32_t)(i & 1) * STAGE_BYTES;
        if (i + 1 < nch) {
            load_chunk(sb + (uint32_t)((i + 1) & 1) * STAGE_BYTES, xh, xl, yh, yl, Kg, (i + 1) * KCH, tid);
            CP_COMMIT();
            CP_WAIT(1);
        } else {
            CP_WAIT(0);
        }
        __syncthreads();

        uint32_t sAh = sb + stage;
        uint32_t sAl = sAh + TILE_BYTES;
        uint32_t sBh = sAl + TILE_BYTES;
        uint32_t sBl = sBh + TILE_BYTES;

        uint32_t ah[4][4], al[4][4], bh[4][2], bl[4][2];
        #pragma unroll
        for (int mi = 0; mi < 4; mi++) {
            uint32_t o = aoff + mi * 16 * TROWB;
            ah[mi][0] = lds32(sAh + o);
            ah[mi][1] = lds32(sAh + o + 8 * TROWB);
            ah[mi][2] = lds32(sAh + o + 16);
            ah[mi][3] = lds32(sAh + o + 8 * TROWB + 16);
            al[mi][0] = lds32(sAl + o);
            al[mi][1] = lds32(sAl + o + 8 * TROWB);
            al[mi][2] = lds32(sAl + o + 16);
            al[mi][3] = lds32(sAl + o + 8 * TROWB + 16);
        }
        #pragma unroll
        for (int ni = 0; ni < 4; ni++) {
            uint32_t o = boff + ni * 8 * TROWB;
            bh[ni][0] = lds32(sBh + o);
            bh[ni][1] = lds32(sBh + o + 16);
            bl[ni][0] = lds32(sBl + o);
            bl[ni][1] = lds32(sBl + o + 16);
        }
        #pragma unroll
        for (int mi = 0; mi < 4; mi++)
            #pragma unroll
            for (int ni = 0; ni < 4; ni++) {
                mma_bf16(acc[mi][ni], ah[mi], bh[ni]);
                mma_bf16(acc[mi][ni], ah[mi], bl[ni]);
                mma_bf16(acc[mi][ni], al[mi], bh[ni]);
            }
        __syncthreads();
    }

    // epilogue: write fp32 D  (c0,c1 at row g; c2,c3 at row g+8; cols 2t,2t+1)
    float* db = D + (size_t)b * Mg * Ng;
    #pragma unroll
    for (int mi = 0; mi < 4; mi++) {
        int gr = bi + warp_m0 + mi * 16 + g;
        #pragma unroll
        for (int ni = 0; ni < 4; ni++) {
            int gc = bj + warp_n0 + ni * 8 + t * 2;
            float2 v0 = make_float2(acc[mi][ni][0], acc[mi][ni][1]);
            float2 v1 = make_float2(acc[mi][ni][2], acc[mi][ni][3]);
            *reinterpret_cast<float2*>(db + (size_t)gr * Ng + gc) = v0;
            *reinterpret_cast<float2*>(db + (size_t)(gr + 8) * Ng + gc) = v1;
        }
    }
}

// ---------------- row softmax: fp32 scores -> bf16 hi/lo probs ----------------
__global__ void softmax_rows(int N) {
    extern __shared__ float srow[];
    __shared__ float red[33];
    size_t row = blockIdx.x;
    const float* p = g_scores + row * (size_t)N;
    int tid = threadIdx.x, bd = blockDim.x;

    float m = -1e30f;
    for (int j = tid; j < N; j += bd) {
        float v = p[j];
        srow[j] = v;
        m = fmaxf(m, v);
    }
    #pragma unroll
    for (int o = 16; o > 0; o >>= 1) m = fmaxf(m, __shfl_xor_sync(0xffffffffu, m, o));
    if ((tid & 31) == 0) red[tid >> 5] = m;
    __syncthreads();
    if (tid < 32) {
        float v = (tid < (bd >> 5)) ? red[tid] : -1e30f;
        #pragma unroll
        for (int o = 16; o > 0; o >>= 1) v = fmaxf(v, __shfl_xor_sync(0xffffffffu, v, o));
        if (tid == 0) red[32] = v;
    }
    __syncthreads();
    m = red[32];

    float s = 0.f;
    for (int j = tid; j < N; j += bd) {
        float e = expf(srow[j] - m);
        srow[j] = e;
        s += e;
    }
    __syncthreads();
    #pragma unroll
    for (int o = 16; o > 0; o >>= 1) s += __shfl_xor_sync(0xffffffffu, s, o);
    if ((tid & 31) == 0) red[tid >> 5] = s;
    __syncthreads();
    if (tid < 32) {
        float v = (tid < (bd >> 5)) ? red[tid] : 0.f;
        #pragma unroll
        for (int o = 16; o > 0; o >>= 1) v += __shfl_xor_sync(0xffffffffu, v, o);
        if (tid == 0) red[32] = v;
    }
    __syncthreads();
    float inv = 1.0f / red[32];
    size_t off = row * (size_t)N;
    for (int j = tid; j < N; j += bd) {
        float pv = srow[j] * inv;
        __nv_bfloat16 h = __float2bfloat16(pv);
        g_Ahi[off + j] = h;
        g_Alo[off + j] = __float2bfloat16(pv - __bfloat162float(h));
    }
}

// ---------------- loss epilogue from [M|T] ----------------
__global__ void loss_epilogue(const float* __restrict__ cin, const float* __restrict__ cs,
                              int N, int C, float inv_count, int total) {
    int i = blockIdx.x * blockDim.x + threadIdx.x;
    float local = 0.f;
    if (i < total) {
        int c = i % C;
        int r = i / C;          // = b*N + n
        int b = r / N;
        float m = g_MT[(size_t)r * 2 * C + c];
        float t = g_MT[(size_t)r * 2 * C + C + c];
        float s2 = t - m * m;
        float s = sqrtf(fmaxf(s2, EPS_VAR));
        float nc = fmaf(cin[i], g_ac[b * C + c], g_bc[b * C + c]);
        float aat = fmaf(s, nc, m);
        float d = cs[i] - aat;
        local = d * d * inv_count;
    }
    #pragma unroll
    for (int o = 16; o > 0; o >>= 1) local += __shfl_xor_sync(0xffffffffu, local, o);
    __shared__ float red[8];
    int tid = threadIdx.x;
    if ((tid & 31) == 0) red[tid >> 5] = local;
    __syncthreads();
    if (tid == 0) {
        float t = 0.f;
        #pragma unroll
        for (int k = 0; k < 8; k++) t += red[k];
        atomicAdd(&g_loss, (double)t);
    }
}

__global__ void write_out_kernel(float* out) { out[0] = (float)g_loss; }

// ---------------- host launcher ----------------
extern "C" void kernel_launch(void* const* d_in, const int* in_sizes, int n_in,
                              void* d_out, int out_size) {
    (void)in_sizes; (void)n_in; (void)out_size;
    const int B = 4;
    struct P { int i_cs, i_c, i_s, i_cc, i_sc, N, C, Cc; };
    P ps[3] = {
        { 0, 1, 2, 3, 4, 4096, 256,  448},
        { 5, 6, 7, 8, 9, 1024, 512,  960},
        {10,11,12,13,14, 256, 512, 1472},
    };

    zero_loss_kernel<<<1, 1>>>();

    for (int s = 0; s < 3; s++) {
        const P& p = ps[s];
        const float* cs = (const float*)d_in[p.i_cs];
        const float* c  = (const float*)d_in[p.i_c];
        const float* st = (const float*)d_in[p.i_s];
        const float* cc = (const float*)d_in[p.i_cc];
        const float* sc = (const float*)d_in[p.i_sc];

        zero_sums_kernel<<<(SMAX + 255) / 256, 256>>>();

        dim3 gs(B, p.N / 8);
        stats_partial_t<0><<<gs, 256>>>(cc, p.N, p.Cc, 8);
        stats_partial_t<1><<<gs, 256>>>(sc, p.N, p.Cc, 8);
        stats_partial_t<2><<<gs, 256>>>(c,  p.N, p.C,  8);
        stats_final_t<0><<<(B * p.Cc + 255) / 256, 256>>>(p.N, p.Cc, B);
        stats_final_t<1><<<(B * p.Cc + 255) / 256, 256>>>(p.N, p.Cc, B);
        stats_final_t<2><<<(B * p.C  + 255) / 256, 256>>>(p.N, p.C,  B);

        int totQ = B * p.N * p.Cc;
        prep_split_affine<0><<<(totQ + 255) / 256, 256>>>(cc, totQ, p.Cc, p.N * p.Cc);
        prep_split_affine<1><<<(totQ + 255) / 256, 256>>>(sc, totQ, p.Cc, p.N * p.Cc);

        dim3 gw(p.N / 32, p.C / 32, B);
        prep_w<<<gw, dim3(32, 8)>>>(st, p.N, p.C);

        // scores = Qn * Kn^T
        dim3 g1(p.N / 128, p.N / 128, B);
        gemm_bf16split<0><<<g1, 256, GEMM_SMEM>>>(p.N, p.N, p.Cc);

        softmax_rows<<<B * p.N, 256, p.N * sizeof(float)>>>(p.N);

        // [M|T] = A * W^T
        dim3 g2((2 * p.C) / 128, p.N / 128, B);
        gemm_bf16split<1><<<g2, 256, GEMM_SMEM>>>(p.N, 2 * p.C, p.N);

        int tot = B * p.N * p.C;
        float inv_count = 1.0f / (float)tot;
        loss_epilogue<<<(tot + 255) / 256, 256>>>(c, cs, p.N, p.C, inv_count, tot);
    }

    write_out_kernel<<<1, 1>>>((float*)d_out);
}

// round 6
// speedup vs baseline: 3.0127x; 1.3300x over previous
#include <cuda_runtime.h>
#include <cuda_bf16.h>
#include <cstdint>
#include <math.h>

#define EPS_VAR 1e-9f
#define SMAX (4*1472)

// ---------------- scratch (static device globals; no allocation) ----------------
// Device globals are ONLY referenced from device code (never passed as kernel
// args from host: host would pass the host shadow address, ATS dereferences it).
__device__ float g_scores[(size_t)4*4096*4096];                  // 256MB fp32 scores
__device__ __nv_bfloat16 g_Ahi[(size_t)4*4096*4096];             // softmax probs hi
__device__ __nv_bfloat16 g_Alo[(size_t)4*4096*4096];             // softmax probs lo
__device__ __nv_bfloat16 g_Qhi[7340032], g_Qlo[7340032];
__device__ __nv_bfloat16 g_Khi[7340032], g_Klo[7340032];
__device__ __nv_bfloat16 g_Whi[8388608], g_Wlo[8388608];         // [V^T ; (V^2)^T]
__device__ float g_MT[8388608];                                  // [M | T] output
__device__ float g_sum_q[SMAX], g_ss_q[SMAX], g_aq[SMAX], g_bq[SMAX];
__device__ float g_sum_k[SMAX], g_ss_k[SMAX], g_ak[SMAX], g_bk[SMAX];
__device__ float g_sum_c[SMAX], g_ss_c[SMAX], g_ac[SMAX], g_bc[SMAX];
__device__ double g_loss;

// ---------------- PTX helpers (sm_80-level baseline features only) ----------------
__device__ __forceinline__ uint32_t smem_u32(const void* p){
    uint32_t a; asm("{ .reg .u64 t; cvta.to.shared.u64 t, %1; cvt.u32.u64 %0, t; }" : "=r"(a) : "l"(p)); return a;
}
__device__ __forceinline__ void cp_async16(uint32_t dst, const void* src){
    asm volatile("cp.async.cg.shared.global [%0], [%1], 16;" :: "r"(dst), "l"(src) : "memory");
}
#define CP_COMMIT() asm volatile("cp.async.commit_group;" ::: "memory")
#define CP_WAIT(n)  asm volatile("cp.async.wait_group %0;" :: "n"(n) : "memory")

__device__ __forceinline__ void ldsm4(uint32_t* r, uint32_t addr){
    asm volatile("ldmatrix.sync.aligned.m8n8.x4.shared.b16 {%0,%1,%2,%3}, [%4];"
        : "=r"(r[0]), "=r"(r[1]), "=r"(r[2]), "=r"(r[3]) : "r"(addr));
}
__device__ __forceinline__ void ldsm2(uint32_t* r, uint32_t addr){
    asm volatile("ldmatrix.sync.aligned.m8n8.x2.shared.b16 {%0,%1}, [%2];"
        : "=r"(r[0]), "=r"(r[1]) : "r"(addr));
}
__device__ __forceinline__ void mma_bf16(float* c, const uint32_t* a, const uint32_t* b){
    asm volatile("mma.sync.aligned.m16n8k16.row.col.f32.bf16.bf16.f32 "
        "{%0,%1,%2,%3}, {%4,%5,%6,%7}, {%8,%9}, {%0,%1,%2,%3};"
        : "+f"(c[0]), "+f"(c[1]), "+f"(c[2]), "+f"(c[3])
        : "r"(a[0]), "r"(a[1]), "r"(a[2]), "r"(a[3]), "r"(b[0]), "r"(b[1]));
}

// ---------------- small kernels ----------------
__global__ void zero_loss_kernel() { g_loss = 0.0; }

__global__ void zero_sums_kernel() {
    int i = blockIdx.x * blockDim.x + threadIdx.x;
    if (i < SMAX) {
        g_sum_q[i] = 0.f; g_ss_q[i] = 0.f;
        g_sum_k[i] = 0.f; g_ss_k[i] = 0.f;
        g_sum_c[i] = 0.f; g_ss_c[i] = 0.f;
    }
}

template<int T>
__global__ void stats_partial_t(const float* __restrict__ x, int N, int C, int rowsPerChunk) {
    float* gsum = (T == 0) ? g_sum_q : (T == 1) ? g_sum_k : g_sum_c;
    float* gss  = (T == 0) ? g_ss_q  : (T == 1) ? g_ss_k  : g_ss_c;
    int b = blockIdx.x, chunk = blockIdx.y;
    int r0 = chunk * rowsPerChunk;
    for (int c = threadIdx.x; c < C; c += blockDim.x) {
        float s = 0.f, ss = 0.f;
        const float* p = x + ((size_t)b * N + r0) * C + c;
        for (int r = 0; r < rowsPerChunk; r++) {
            float v = p[(size_t)r * C];
            s += v; ss = fmaf(v, v, ss);
        }
        atomicAdd(&gsum[b * C + c], s);
        atomicAdd(&gss[b * C + c], ss);
    }
}

template<int T>
__global__ void stats_final_t(int N, int C, int B) {
    const float* gsum = (T == 0) ? g_sum_q : (T == 1) ? g_sum_k : g_sum_c;
    const float* gss  = (T == 0) ? g_ss_q  : (T == 1) ? g_ss_k  : g_ss_c;
    float* ga = (T == 0) ? g_aq : (T == 1) ? g_ak : g_ac;
    float* gb = (T == 0) ? g_bq : (T == 1) ? g_bk : g_bc;
    int i = blockIdx.x * blockDim.x + threadIdx.x;
    if (i < B * C) {
        float invN = 1.0f / (float)N;
        float mean = gsum[i] * invN;
        float var  = gss[i] * invN - mean * mean;
        float r = rsqrtf(var + 1e-5f);
        ga[i] = r;
        gb[i] = -mean * r;
    }
}

// normalize + split fp32 -> bf16 hi/lo.  T=0: comb_c -> Q;  T=1: comb_s -> K
template<int T>
__global__ void prep_split_affine(const float* __restrict__ x,
                                  int total, int C, int perBatch) {
    const float* ga = (T == 0) ? g_aq : g_ak;
    const float* gb = (T == 0) ? g_bq : g_bk;
    __nv_bfloat16* hi = (T == 0) ? g_Qhi : g_Khi;
    __nv_bfloat16* lo = (T == 0) ? g_Qlo : g_Klo;
    int i = blockIdx.x * blockDim.x + threadIdx.x;
    if (i >= total) return;
    int b = i / perBatch;
    int ch = i % C;
    float y = fmaf(x[i], ga[b * C + ch], gb[b * C + ch]);
    __nv_bfloat16 h = __float2bfloat16(y);
    hi[i] = h;
    lo[i] = __float2bfloat16(y - __bfloat162float(h));
}

// W = [V^T ; (V^2)^T]  (2C x N per batch), bf16 hi only (2-term AV split)
__global__ void prep_w(const float* __restrict__ v, int N, int C) {
    __shared__ float tile[32][33];
    int b = blockIdx.z;
    int j0 = blockIdx.x * 32, c0 = blockIdx.y * 32;
    int tx = threadIdx.x, ty = threadIdx.y;  // 32 x 8
    const float* vb = v + (size_t)b * N * C;
    #pragma unroll
    for (int r = 0; r < 4; r++)
        tile[ty + 8 * r][tx] = vb[(size_t)(j0 + ty + 8 * r) * C + c0 + tx];
    __syncthreads();
    size_t base = (size_t)b * 2 * C * N;
    #pragma unroll
    for (int r = 0; r < 4; r++) {
        int c = c0 + ty + 8 * r, j = j0 + tx;
        float val = tile[tx][ty + 8 * r];
        g_Whi[base + (size_t)c * N + j] = __float2bfloat16(val);
        g_Whi[base + (size_t)(C + c) * N + j] = __float2bfloat16(val * val);
    }
}

// ---------------- mma.sync split-bf16 GEMM: D = X * Y^T ----------------
// MODE 0 (3-term): X = Qn (Kg=Cc), Y = Kn, D = g_scores
// MODE 1 (2-term): X = A  (Kg=N),  Y = Whi only, D = g_MT
// 128x128 block tile, 8 warps of 64x32, K-chunk 16, cp.async double buffered.
// smem tile: 128 rows x 16 bf16, row stride 48B (ldmatrix conflict-free:
// words 12r mod 32 distinct over the 8-lane phase). 4x6144x2 = 49152B.
#define KCH 16
#define TROWB 48
#define TILE_BYTES (128 * TROWB)
#define STAGE_BYTES (4 * TILE_BYTES)
#define GEMM_SMEM (2 * STAGE_BYTES)

template<int NT>
__device__ __forceinline__ void load_chunk(uint32_t sbase,
        const __nv_bfloat16* xh, const __nv_bfloat16* xl,
        const __nv_bfloat16* yh, const __nv_bfloat16* yl,
        int Kg, int k0, int tid) {
    const __nv_bfloat16* srcs[4] = { xh, xl, yh, yl };
    int r = tid >> 1, h = tid & 1;          // 256 16B vectors: 128 rows x 2 halves
    #pragma unroll
    for (int a = 0; a < NT; a++)
        cp_async16(sbase + a * TILE_BYTES + r * TROWB + h * 16,
                   srcs[a] + (size_t)r * Kg + k0 + h * 8);
}

template<int MODE>
__global__ __launch_bounds__(256)
void gemm_bf16split(int Mg, int Ng, int Kg) {
    extern __shared__ char smem[];
    uint32_t sb = smem_u32(smem);
    int tid = threadIdx.x;
    int wid = tid >> 5, lane = tid & 31;
    int g = lane >> 2, t = lane & 3;
    int warp_m0 = (wid >> 2) << 6;   // 0 or 64
    int warp_n0 = (wid & 3) << 5;    // 0,32,64,96
    int b = blockIdx.z;
    int bi = blockIdx.y * 128, bj = blockIdx.x * 128;
    const int NT = (MODE == 0) ? 4 : 3;   // tiles per stage actually loaded

    const __nv_bfloat16* Xhi = (MODE == 0) ? g_Qhi : g_Ahi;
    const __nv_bfloat16* Xlo = (MODE == 0) ? g_Qlo : g_Alo;
    const __nv_bfloat16* Yhi = (MODE == 0) ? g_Khi : g_Whi;
    const __nv_bfloat16* Ylo = (MODE == 0) ? g_Klo : g_Whi;   // unused in MODE 1
    float* D = (MODE == 0) ? g_scores : g_MT;

    const __nv_bfloat16* xh = Xhi + (size_t)b * Mg * Kg + (size_t)bi * Kg;
    const __nv_bfloat16* xl = Xlo + (size_t)b * Mg * Kg + (size_t)bi * Kg;
    const __nv_bfloat16* yh = Yhi + (size_t)b * Ng * Kg + (size_t)bj * Kg;
    const __nv_bfloat16* yl = Ylo + (size_t)b * Ng * Kg + (size_t)bj * Kg;

    float acc[4][4][4];
    #pragma unroll
    for (int i = 0; i < 4; i++)
        #pragma unroll
        for (int j = 0; j < 4; j++)
            #pragma unroll
            for (int k = 0; k < 4; k++) acc[i][j][k] = 0.f;

    int nch = Kg / KCH;

    // ldmatrix lane addressing (within a tile, bytes)
    // A x4: lanes 0-15 -> rows (lane&15), col-half 0; lanes 16-31 -> col-half 1
    uint32_t a_off = (uint32_t)((warp_m0 + (lane & 15)) * TROWB + (lane >> 4) * 16);
    // B x2: lanes 0-7 -> rows (lane&7) col-half 0; lanes 8-15 -> col-half 1
    uint32_t b_off = (uint32_t)((warp_n0 + (lane & 7)) * TROWB + ((lane >> 3) & 1) * 16);

    load_chunk<NT>(sb, xh, xl, yh, yl, Kg, 0, tid);
    CP_COMMIT();

    for (int i = 0; i < nch; i++) {
        uint32_t stage = (uint32_t)(i & 1) * STAGE_BYTES;
        if (i + 1 < nch) {
            load_chunk<NT>(sb + (uint32_t)((i + 1) & 1) * STAGE_BYTES, xh, xl, yh, yl, Kg, (i + 1) * KCH, tid);
            CP_COMMIT();
            CP_WAIT(1);
        } else {
            CP_WAIT(0);
        }
        __syncthreads();

        uint32_t sAh = sb + stage;
        uint32_t sAl = sAh + TILE_BYTES;
        uint32_t sBh = sAl + TILE_BYTES;
        uint32_t sBl = sBh + TILE_BYTES;

        uint32_t ah[4][4], al[4][4], bh[4][2], bl[4][2];
        #pragma unroll
        for (int mi = 0; mi < 4; mi++) {
            uint32_t o = a_off + mi * 16 * TROWB;
            ldsm4(ah[mi], sAh + o);
            ldsm4(al[mi], sAl + o);
        }
        #pragma unroll
        for (int ni = 0; ni < 4; ni++) {
            uint32_t o = b_off + ni * 8 * TROWB;
            ldsm2(bh[ni], sBh + o);
            if (MODE == 0) ldsm2(bl[ni], sBl + o);
        }
        #pragma unroll
        for (int mi = 0; mi < 4; mi++)
            #pragma unroll
            for (int ni = 0; ni < 4; ni++) {
                mma_bf16(acc[mi][ni], ah[mi], bh[ni]);
                if (MODE == 0) mma_bf16(acc[mi][ni], ah[mi], bl[ni]);
                mma_bf16(acc[mi][ni], al[mi], bh[ni]);
            }
        __syncthreads();
    }

    // epilogue: write fp32 D  (c0,c1 at row g; c2,c3 at row g+8; cols 2t,2t+1)
    float* db = D + (size_t)b * Mg * Ng;
    #pragma unroll
    for (int mi = 0; mi < 4; mi++) {
        int gr = bi + warp_m0 + mi * 16 + g;
        #pragma unroll
        for (int ni = 0; ni < 4; ni++) {
            int gc = bj + warp_n0 + ni * 8 + t * 2;
            float2 v0 = make_float2(acc[mi][ni][0], acc[mi][ni][1]);
            float2 v1 = make_float2(acc[mi][ni][2], acc[mi][ni][3]);
            *reinterpret_cast<float2*>(db + (size_t)gr * Ng + gc) = v0;
            *reinterpret_cast<float2*>(db + (size_t)(gr + 8) * Ng + gc) = v1;
        }
    }
}

// ---------------- row softmax: fp32 scores -> bf16 hi/lo probs ----------------
__global__ void softmax_rows(int N) {
    extern __shared__ float srow[];
    __shared__ float red[33];
    size_t row = blockIdx.x;
    const float* p = g_scores + row * (size_t)N;
    int tid = threadIdx.x, bd = blockDim.x;

    float m = -1e30f;
    for (int j = tid; j < N; j += bd) {
        float v = p[j];
        srow[j] = v;
        m = fmaxf(m, v);
    }
    #pragma unroll
    for (int o = 16; o > 0; o >>= 1) m = fmaxf(m, __shfl_xor_sync(0xffffffffu, m, o));
    if ((tid & 31) == 0) red[tid >> 5] = m;
    __syncthreads();
    if (tid < 32) {
        float v = (tid < (bd >> 5)) ? red[tid] : -1e30f;
        #pragma unroll
        for (int o = 16; o > 0; o >>= 1) v = fmaxf(v, __shfl_xor_sync(0xffffffffu, v, o));
        if (tid == 0) red[32] = v;
    }
    __syncthreads();
    m = red[32];

    float s = 0.f;
    for (int j = tid; j < N; j += bd) {
        float e = expf(srow[j] - m);
        srow[j] = e;
        s += e;
    }
    __syncthreads();
    #pragma unroll
    for (int o = 16; o > 0; o >>= 1) s += __shfl_xor_sync(0xffffffffu, s, o);
    if ((tid & 31) == 0) red[tid >> 5] = s;
    __syncthreads();
    if (tid < 32) {
        float v = (tid < (bd >> 5)) ? red[tid] : 0.f;
        #pragma unroll
        for (int o = 16; o > 0; o >>= 1) v += __shfl_xor_sync(0xffffffffu, v, o);
        if (tid == 0) red[32] = v;
    }
    __syncthreads();
    float inv = 1.0f / red[32];
    size_t off = row * (size_t)N;
    for (int j = tid; j < N; j += bd) {
        float pv = srow[j] * inv;
        __nv_bfloat16 h = __float2bfloat16(pv);
        g_Ahi[off + j] = h;
        g_Alo[off + j] = __float2bfloat16(pv - __bfloat162float(h));
    }
}

// ---------------- loss epilogue from [M|T] ----------------
__global__ void loss_epilogue(const float* __restrict__ cin, const float* __restrict__ cs,
                              int N, int C, float inv_count, int total) {
    int i = blockIdx.x * blockDim.x + threadIdx.x;
    float local = 0.f;
    if (i < total) {
        int c = i % C;
        int r = i / C;          // = b*N + n
        int b = r / N;
        float m = g_MT[(size_t)r * 2 * C + c];
        float t = g_MT[(size_t)r * 2 * C + C + c];
        float s2 = t - m * m;
        float s = sqrtf(fmaxf(s2, EPS_VAR));
        float nc = fmaf(cin[i], g_ac[b * C + c], g_bc[b * C + c]);
        float aat = fmaf(s, nc, m);
        float d = cs[i] - aat;
        local = d * d * inv_count;
    }
    #pragma unroll
    for (int o = 16; o > 0; o >>= 1) local += __shfl_xor_sync(0xffffffffu, local, o);
    __shared__ float red[8];
    int tid = threadIdx.x;
    if ((tid & 31) == 0) red[tid >> 5] = local;
    __syncthreads();
    if (tid == 0) {
        float t = 0.f;
        #pragma unroll
        for (int k = 0; k < 8; k++) t += red[k];
        atomicAdd(&g_loss, (double)t);
    }
}

__global__ void write_out_kernel(float* out) { out[0] = (float)g_loss; }

// ---------------- host launcher ----------------
extern "C" void kernel_launch(void* const* d_in, const int* in_sizes, int n_in,
                              void* d_out, int out_size) {
    (void)in_sizes; (void)n_in; (void)out_size;
    const int B = 4;
    struct P { int i_cs, i_c, i_s, i_cc, i_sc, N, C, Cc; };
    P ps[3] = {
        { 0, 1, 2, 3, 4, 4096, 256,  448},
        { 5, 6, 7, 8, 9, 1024, 512,  960},
        {10,11,12,13,14, 256, 512, 1472},
    };

    zero_loss_kernel<<<1, 1>>>();

    for (int s = 0; s < 3; s++) {
        const P& p = ps[s];
        const float* cs = (const float*)d_in[p.i_cs];
        const float* c  = (const float*)d_in[p.i_c];
        const float* st = (const float*)d_in[p.i_s];
        const float* cc = (const float*)d_in[p.i_cc];
        const float* sc = (const float*)d_in[p.i_sc];

        zero_sums_kernel<<<(SMAX + 255) / 256, 256>>>();

        dim3 gs(B, p.N / 8);
        stats_partial_t<0><<<gs, 256>>>(cc, p.N, p.Cc, 8);
        stats_partial_t<1><<<gs, 256>>>(sc, p.N, p.Cc, 8);
        stats_partial_t<2><<<gs, 256>>>(c,  p.N, p.C,  8);
        stats_final_t<0><<<(B * p.Cc + 255) / 256, 256>>>(p.N, p.Cc, B);
        stats_final_t<1><<<(B * p.Cc + 255) / 256, 256>>>(p.N, p.Cc, B);
        stats_final_t<2><<<(B * p.C  + 255) / 256, 256>>>(p.N, p.C,  B);

        int totQ = B * p.N * p.Cc;
        prep_split_affine<0><<<(totQ + 255) / 256, 256>>>(cc, totQ, p.Cc, p.N * p.Cc);
        prep_split_affine<1><<<(totQ + 255) / 256, 256>>>(sc, totQ, p.Cc, p.N * p.Cc);

        dim3 gw(p.N / 32, p.C / 32, B);
        prep_w<<<gw, dim3(32, 8)>>>(st, p.N, p.C);

        // scores = Qn * Kn^T (3-term)
        dim3 g1(p.N / 128, p.N / 128, B);
        gemm_bf16split<0><<<g1, 256, GEMM_SMEM>>>(p.N, p.N, p.Cc);

        softmax_rows<<<B * p.N, 256, p.N * sizeof(float)>>>(p.N);

        // [M|T] = A * W^T (2-term)
        dim3 g2((2 * p.C) / 128, p.N / 128, B);
        gemm_bf16split<1><<<g2, 256, GEMM_SMEM>>>(p.N, 2 * p.C, p.N);

        int tot = B * p.N * p.C;
        float inv_count = 1.0f / (float)tot;
        loss_epilogue<<<(tot + 255) / 256, 256>>>(c, cs, p.N, p.C, inv_count, tot);
    }

    write_out_kernel<<<1, 1>>>((float*)d_out);
}

// round 7
// speedup vs baseline: 3.3825x; 1.1227x over previous
#include <cuda_runtime.h>
#include <cuda_fp16.h>
#include <cstdint>
#include <math.h>

#define EPS_VAR 1e-9f
#define SMAX (4*1472)

// ---------------- scratch (static device globals; no allocation) ----------------
// Device globals are ONLY referenced from device code (never passed as kernel
// args from host: host would pass the host shadow address, ATS dereferences it).
// Arrays hold all three scales at disjoint offsets so scales can run concurrently.
__device__ float  g_scores[71565312];            // fp32 scores (all scales)
__device__ __half g_Ahi[71565312];               // softmax probs hi
__device__ __half g_Alo[71565312];               // softmax probs lo
__device__ __half g_Qhi[13631488], g_Qlo[13631488];
__device__ __half g_Khi[13631488], g_Klo[13631488];
__device__ __half g_Whi[13631488];               // [V^T ; (V^2)^T] (hi only, 2-term AV)
__device__ float  g_MT[13631488];                // [M | T] outputs
__device__ float g_sum_q[3*SMAX], g_ss_q[3*SMAX], g_aq[3*SMAX], g_bq[3*SMAX];
__device__ float g_sum_k[3*SMAX], g_ss_k[3*SMAX], g_ak[3*SMAX], g_bk[3*SMAX];
__device__ float g_sum_c[3*SMAX], g_ss_c[3*SMAX], g_ac[3*SMAX], g_bc[3*SMAX];
__device__ double g_loss;

// ---------------- PTX helpers (sm_80-level baseline features only) ----------------
__device__ __forceinline__ uint32_t smem_u32(const void* p){
    uint32_t a; asm("{ .reg .u64 t; cvta.to.shared.u64 t, %1; cvt.u32.u64 %0, t; }" : "=r"(a) : "l"(p)); return a;
}
__device__ __forceinline__ void cp_async16(uint32_t dst, const void* src){
    asm volatile("cp.async.cg.shared.global [%0], [%1], 16;" :: "r"(dst), "l"(src) : "memory");
}
#define CP_COMMIT() asm volatile("cp.async.commit_group;" ::: "memory")
#define CP_WAIT(n)  asm volatile("cp.async.wait_group %0;" :: "n"(n) : "memory")

__device__ __forceinline__ void ldsm4(uint32_t* r, uint32_t addr){
    asm volatile("ldmatrix.sync.aligned.m8n8.x4.shared.b16 {%0,%1,%2,%3}, [%4];"
        : "=r"(r[0]), "=r"(r[1]), "=r"(r[2]), "=r"(r[3]) : "r"(addr));
}
__device__ __forceinline__ void ldsm2(uint32_t* r, uint32_t addr){
    asm volatile("ldmatrix.sync.aligned.m8n8.x2.shared.b16 {%0,%1}, [%2];"
        : "=r"(r[0]), "=r"(r[1]) : "r"(addr));
}
__device__ __forceinline__ void mma_f16(float* c, const uint32_t* a, const uint32_t* b){
    asm volatile("mma.sync.aligned.m16n8k16.row.col.f32.f16.f16.f32 "
        "{%0,%1,%2,%3}, {%4,%5,%6,%7}, {%8,%9}, {%0,%1,%2,%3};"
        : "+f"(c[0]), "+f"(c[1]), "+f"(c[2]), "+f"(c[3])
        : "r"(a[0]), "r"(a[1]), "r"(a[2]), "r"(a[3]), "r"(b[0]), "r"(b[1]));
}

// ---------------- small kernels ----------------
__global__ void zero_loss_kernel() { g_loss = 0.0; }

__global__ void zero_sums_kernel(int soff) {
    int i = blockIdx.x * blockDim.x + threadIdx.x;
    if (i < SMAX) {
        g_sum_q[soff + i] = 0.f; g_ss_q[soff + i] = 0.f;
        g_sum_k[soff + i] = 0.f; g_ss_k[soff + i] = 0.f;
        g_sum_c[soff + i] = 0.f; g_ss_c[soff + i] = 0.f;
    }
}

template<int T>
__global__ void stats_partial_t(const float* __restrict__ x, int N, int C, int rowsPerChunk, int soff) {
    float* gsum = ((T == 0) ? g_sum_q : (T == 1) ? g_sum_k : g_sum_c) + soff;
    float* gss  = ((T == 0) ? g_ss_q  : (T == 1) ? g_ss_k  : g_ss_c) + soff;
    int b = blockIdx.x, chunk = blockIdx.y;
    int r0 = chunk * rowsPerChunk;
    for (int c = threadIdx.x; c < C; c += blockDim.x) {
        float s = 0.f, ss = 0.f;
        const float* p = x + ((size_t)b * N + r0) * C + c;
        for (int r = 0; r < rowsPerChunk; r++) {
            float v = p[(size_t)r * C];
            s += v; ss = fmaf(v, v, ss);
        }
        atomicAdd(&gsum[b * C + c], s);
        atomicAdd(&gss[b * C + c], ss);
    }
}

template<int T>
__global__ void stats_final_t(int N, int C, int B, int soff) {
    const float* gsum = ((T == 0) ? g_sum_q : (T == 1) ? g_sum_k : g_sum_c) + soff;
    const float* gss  = ((T == 0) ? g_ss_q  : (T == 1) ? g_ss_k  : g_ss_c) + soff;
    float* ga = ((T == 0) ? g_aq : (T == 1) ? g_ak : g_ac) + soff;
    float* gb = ((T == 0) ? g_bq : (T == 1) ? g_bk : g_bc) + soff;
    int i = blockIdx.x * blockDim.x + threadIdx.x;
    if (i < B * C) {
        float invN = 1.0f / (float)N;
        float mean = gsum[i] * invN;
        float var  = gss[i] * invN - mean * mean;
        float r = rsqrtf(var + 1e-5f);
        ga[i] = r;
        gb[i] = -mean * r;
    }
}

// normalize + split fp32 -> fp16 hi/lo.  T=0: comb_c -> Q;  T=1: comb_s -> K
template<int T>
__global__ void prep_split_affine(const float* __restrict__ x,
                                  int total, int C, int perBatch, int soff, size_t qoff) {
    const float* ga = ((T == 0) ? g_aq : g_ak) + soff;
    const float* gb = ((T == 0) ? g_bq : g_bk) + soff;
    __half* hi = ((T == 0) ? g_Qhi : g_Khi) + qoff;
    __half* lo = ((T == 0) ? g_Qlo : g_Klo) + qoff;
    int i = blockIdx.x * blockDim.x + threadIdx.x;
    if (i >= total) return;
    int b = i / perBatch;
    int ch = i % C;
    float y = fmaf(x[i], ga[b * C + ch], gb[b * C + ch]);
    __half h = __float2half(y);
    hi[i] = h;
    lo[i] = __float2half(y - __half2float(h));
}

// W = [V^T ; (V^2)^T]  (2C x N per batch), fp16 hi only
__global__ void prep_w(const float* __restrict__ v, int N, int C, size_t woff) {
    __shared__ float tile[32][33];
    int b = blockIdx.z;
    int j0 = blockIdx.x * 32, c0 = blockIdx.y * 32;
    int tx = threadIdx.x, ty = threadIdx.y;  // 32 x 8
    const float* vb = v + (size_t)b * N * C;
    #pragma unroll
    for (int r = 0; r < 4; r++)
        tile[ty + 8 * r][tx] = vb[(size_t)(j0 + ty + 8 * r) * C + c0 + tx];
    __syncthreads();
    __half* w = g_Whi + woff + (size_t)b * 2 * C * N;
    #pragma unroll
    for (int r = 0; r < 4; r++) {
        int c = c0 + ty + 8 * r, j = j0 + tx;
        float val = tile[tx][ty + 8 * r];
        w[(size_t)c * N + j] = __float2half(val);
        w[(size_t)(C + c) * N + j] = __float2half(val * val);
    }
}

// ---------------- mma.sync split-fp16 GEMM: D = X * Y^T ----------------
// MODE 0 (3-term): X = Qn (Kg=Cc), Y = Kn, D = scores
// MODE 1 (2-term): X = A  (Kg=N),  Y = Whi, D = MT
// 128x128 block tile, 8 warps of 64x32, K-chunk 16, cp.async double buffered.
// smem tile: 128 rows x 16 fp16, row stride 48B (ldmatrix conflict-free).
#define KCH 16
#define TROWB 48
#define TILE_BYTES (128 * TROWB)
#define STAGE_BYTES (4 * TILE_BYTES)
#define GEMM_SMEM (2 * STAGE_BYTES)

template<int NT>
__device__ __forceinline__ void load_chunk(uint32_t sbase,
        const __half* xh, const __half* xl,
        const __half* yh, const __half* yl,
        int Kg, int k0, int tid) {
    const __half* srcs[4] = { xh, xl, yh, yl };
    int r = tid >> 1, h = tid & 1;          // 256 16B vectors: 128 rows x 2 halves
    #pragma unroll
    for (int a = 0; a < NT; a++)
        cp_async16(sbase + a * TILE_BYTES + r * TROWB + h * 16,
                   srcs[a] + (size_t)r * Kg + k0 + h * 8);
}

template<int MODE>
__global__ __launch_bounds__(256)
void gemm_f16split(int Mg, int Ng, int Kg, size_t xoff, size_t yoff, size_t doff) {
    extern __shared__ char smem[];
    uint32_t sb = smem_u32(smem);
    int tid = threadIdx.x;
    int wid = tid >> 5, lane = tid & 31;
    int g = lane >> 2, t = lane & 3;
    int warp_m0 = (wid >> 2) << 6;   // 0 or 64
    int warp_n0 = (wid & 3) << 5;    // 0,32,64,96
    int b = blockIdx.z;
    int bi = blockIdx.y * 128, bj = blockIdx.x * 128;
    const int NT = (MODE == 0) ? 4 : 3;

    const __half* Xhi = ((MODE == 0) ? g_Qhi : g_Ahi) + xoff;
    const __half* Xlo = ((MODE == 0) ? g_Qlo : g_Alo) + xoff;
    const __half* Yhi = ((MODE == 0) ? g_Khi : g_Whi) + yoff;
    const __half* Ylo = ((MODE == 0) ? g_Klo : g_Whi) + yoff;   // unused in MODE 1
    float* D = ((MODE == 0) ? g_scores : g_MT) + doff;

    const __half* xh = Xhi + (size_t)b * Mg * Kg + (size_t)bi * Kg;
    const __half* xl = Xlo + (size_t)b * Mg * Kg + (size_t)bi * Kg;
    const __half* yh = Yhi + (size_t)b * Ng * Kg + (size_t)bj * Kg;
    const __half* yl = Ylo + (size_t)b * Ng * Kg + (size_t)bj * Kg;

    float acc[4][4][4];
    #pragma unroll
    for (int i = 0; i < 4; i++)
        #pragma unroll
        for (int j = 0; j < 4; j++)
            #pragma unroll
            for (int k = 0; k < 4; k++) acc[i][j][k] = 0.f;

    int nch = Kg / KCH;

    uint32_t a_off = (uint32_t)((warp_m0 + (lane & 15)) * TROWB + (lane >> 4) * 16);
    uint32_t b_off = (uint32_t)((warp_n0 + (lane & 7)) * TROWB + ((lane >> 3) & 1) * 16);

    load_chunk<NT>(sb, xh, xl, yh, yl, Kg, 0, tid);
    CP_COMMIT();

    for (int i = 0; i < nch; i++) {
        uint32_t stage = (uint32_t)(i & 1) * STAGE_BYTES;
        if (i + 1 < nch) {
            load_chunk<NT>(sb + (uint32_t)((i + 1) & 1) * STAGE_BYTES, xh, xl, yh, yl, Kg, (i + 1) * KCH, tid);
            CP_COMMIT();
            CP_WAIT(1);
        } else {
            CP_WAIT(0);
        }
        __syncthreads();

        uint32_t sAh = sb + stage;
        uint32_t sAl = sAh + TILE_BYTES;
        uint32_t sBh = sAl + TILE_BYTES;
        uint32_t sBl = sBh + TILE_BYTES;

        uint32_t ah[4][4], al[4][4], bh[4][2], bl[4][2];
        #pragma unroll
        for (int mi = 0; mi < 4; mi++) {
            uint32_t o = a_off + mi * 16 * TROWB;
            ldsm4(ah[mi], sAh + o);
            ldsm4(al[mi], sAl + o);
        }
        #pragma unroll
        for (int ni = 0; ni < 4; ni++) {
            uint32_t o = b_off + ni * 8 * TROWB;
            ldsm2(bh[ni], sBh + o);
            if (MODE == 0) ldsm2(bl[ni], sBl + o);
        }
        #pragma unroll
        for (int mi = 0; mi < 4; mi++)
            #pragma unroll
            for (int ni = 0; ni < 4; ni++) {
                mma_f16(acc[mi][ni], ah[mi], bh[ni]);
                if (MODE == 0) mma_f16(acc[mi][ni], ah[mi], bl[ni]);
                mma_f16(acc[mi][ni], al[mi], bh[ni]);
            }
        __syncthreads();
    }

    float* db = D + (size_t)b * Mg * Ng;
    #pragma unroll
    for (int mi = 0; mi < 4; mi++) {
        int gr = bi + warp_m0 + mi * 16 + g;
        #pragma unroll
        for (int ni = 0; ni < 4; ni++) {
            int gc = bj + warp_n0 + ni * 8 + t * 2;
            float2 v0 = make_float2(acc[mi][ni][0], acc[mi][ni][1]);
            float2 v1 = make_float2(acc[mi][ni][2], acc[mi][ni][3]);
            *reinterpret_cast<float2*>(db + (size_t)gr * Ng + gc) = v0;
            *reinterpret_cast<float2*>(db + (size_t)(gr + 8) * Ng + gc) = v1;
        }
    }
}

// ---------------- row softmax: fp32 scores -> fp16 hi/lo probs ----------------
__global__ void softmax_rows(int N, size_t scoff) {
    extern __shared__ float srow[];
    __shared__ float red[33];
    size_t row = blockIdx.x;
    const float* p = g_scores + scoff + row * (size_t)N;
    int tid = threadIdx.x, bd = blockDim.x;

    float m = -1e30f;
    for (int j = tid; j < N; j += bd) {
        float v = p[j];
        srow[j] = v;
        m = fmaxf(m, v);
    }
    #pragma unroll
    for (int o = 16; o > 0; o >>= 1) m = fmaxf(m, __shfl_xor_sync(0xffffffffu, m, o));
    if ((tid & 31) == 0) red[tid >> 5] = m;
    __syncthreads();
    if (tid < 32) {
        float v = (tid < (bd >> 5)) ? red[tid] : -1e30f;
        #pragma unroll
        for (int o = 16; o > 0; o >>= 1) v = fmaxf(v, __shfl_xor_sync(0xffffffffu, v, o));
        if (tid == 0) red[32] = v;
    }
    __syncthreads();
    m = red[32];

    float s = 0.f;
    for (int j = tid; j < N; j += bd) {
        float e = expf(srow[j] - m);
        srow[j] = e;
        s += e;
    }
    __syncthreads();
    #pragma unroll
    for (int o = 16; o > 0; o >>= 1) s += __shfl_xor_sync(0xffffffffu, s, o);
    if ((tid & 31) == 0) red[tid >> 5] = s;
    __syncthreads();
    if (tid < 32) {
        float v = (tid < (bd >> 5)) ? red[tid] : 0.f;
        #pragma unroll
        for (int o = 16; o > 0; o >>= 1) v += __shfl_xor_sync(0xffffffffu, v, o);
        if (tid == 0) red[32] = v;
    }
    __syncthreads();
    float inv = 1.0f / red[32];
    size_t off = scoff + row * (size_t)N;
    for (int j = tid; j < N; j += bd) {
        float pv = srow[j] * inv;
        __half h = __float2half(pv);
        g_Ahi[off + j] = h;
        g_Alo[off + j] = __float2half(pv - __half2float(h));
    }
}

// ---------------- loss epilogue from [M|T] ----------------
__global__ void loss_epilogue(const float* __restrict__ cin, const float* __restrict__ cs,
                              int N, int C, float inv_count, int total,
                              size_t mtoff, int soff) {
    int i = blockIdx.x * blockDim.x + threadIdx.x;
    float local = 0.f;
    if (i < total) {
        int c = i % C;
        int r = i / C;          // = b*N + n
        int b = r / N;
        const float* mt = g_MT + mtoff;
        float m = mt[(size_t)r * 2 * C + c];
        float t = mt[(size_t)r * 2 * C + C + c];
        float s2 = t - m * m;
        float s = sqrtf(fmaxf(s2, EPS_VAR));
        float nc = fmaf(cin[i], g_ac[soff + b * C + c], g_bc[soff + b * C + c]);
        float aat = fmaf(s, nc, m);
        float d = cs[i] - aat;
        local = d * d * inv_count;
    }
    #pragma unroll
    for (int o = 16; o > 0; o >>= 1) local += __shfl_xor_sync(0xffffffffu, local, o);
    __shared__ float red[8];
    int tid = threadIdx.x;
    if ((tid & 31) == 0) red[tid >> 5] = local;
    __syncthreads();
    if (tid == 0) {
        float t = 0.f;
        #pragma unroll
        for (int k = 0; k < 8; k++) t += red[k];
        atomicAdd(&g_loss, (double)t);
    }
}

__global__ void write_out_kernel(float* out) { out[0] = (float)g_loss; }

// ---------------- host launcher ----------------
struct ScaleP { int i_cs, i_c, i_s, i_cc, i_sc, N, C, Cc; size_t qoff, woff, scoff; int soff; };

static void run_scale(const ScaleP& p, void* const* d_in, cudaStream_t st) {
    const int B = 4;
    const float* cs = (const float*)d_in[p.i_cs];
    const float* c  = (const float*)d_in[p.i_c];
    const float* stp= (const float*)d_in[p.i_s];
    const float* cc = (const float*)d_in[p.i_cc];
    const float* sc = (const float*)d_in[p.i_sc];

    zero_sums_kernel<<<(SMAX + 255) / 256, 256, 0, st>>>(p.soff);

    dim3 gs(B, p.N / 8);
    stats_partial_t<0><<<gs, 256, 0, st>>>(cc, p.N, p.Cc, 8, p.soff);
    stats_partial_t<1><<<gs, 256, 0, st>>>(sc, p.N, p.Cc, 8, p.soff);
    stats_partial_t<2><<<gs, 256, 0, st>>>(c,  p.N, p.C,  8, p.soff);
    stats_final_t<0><<<(B * p.Cc + 255) / 256, 256, 0, st>>>(p.N, p.Cc, B, p.soff);
    stats_final_t<1><<<(B * p.Cc + 255) / 256, 256, 0, st>>>(p.N, p.Cc, B, p.soff);
    stats_final_t<2><<<(B * p.C  + 255) / 256, 256, 0, st>>>(p.N, p.C,  B, p.soff);

    int totQ = B * p.N * p.Cc;
    prep_split_affine<0><<<(totQ + 255) / 256, 256, 0, st>>>(cc, totQ, p.Cc, p.N * p.Cc, p.soff, p.qoff);
    prep_split_affine<1><<<(totQ + 255) / 256, 256, 0, st>>>(sc, totQ, p.Cc, p.N * p.Cc, p.soff, p.qoff);

    dim3 gw(p.N / 32, p.C / 32, B);
    prep_w<<<gw, dim3(32, 8), 0, st>>>(stp, p.N, p.C, p.woff);

    dim3 g1(p.N / 128, p.N / 128, B);
    gemm_f16split<0><<<g1, 256, GEMM_SMEM, st>>>(p.N, p.N, p.Cc, p.qoff, p.qoff, p.scoff);

    softmax_rows<<<B * p.N, 256, p.N * sizeof(float), st>>>(p.N, p.scoff);

    dim3 g2((2 * p.C) / 128, p.N / 128, B);
    gemm_f16split<1><<<g2, 256, GEMM_SMEM, st>>>(p.N, 2 * p.C, p.N, p.scoff, p.woff, p.woff);

    int tot = B * p.N * p.C;
    float inv_count = 1.0f / (float)tot;
    loss_epilogue<<<(tot + 255) / 256, 256, 0, st>>>(c, cs, p.N, p.C, inv_count, tot, p.woff, p.soff);
}

extern "C" void kernel_launch(void* const* d_in, const int* in_sizes, int n_in,
                              void* d_out, int out_size) {
    (void)in_sizes; (void)n_in; (void)out_size;

    static bool s_init = false;
    static cudaStream_t s_aux;
    static cudaEvent_t ev_fork, ev_join;
    if (!s_init) {
        cudaStreamCreateWithFlags(&s_aux, cudaStreamNonBlocking);
        cudaEventCreateWithFlags(&ev_fork, cudaEventDisableTiming);
        cudaEventCreateWithFlags(&ev_join, cudaEventDisableTiming);
        s_init = true;
    }

    // per-scale buffer offsets (elements)
    ScaleP ps[3] = {
        { 0, 1, 2, 3, 4, 4096, 256,  448, 0,        0,        0,        0      },
        { 5, 6, 7, 8, 9, 1024, 512,  960, 7340032,  8388608,  67108864, SMAX   },
        {10,11,12,13,14, 256, 512, 1472, 11272192, 12582912, 71303168, 2*SMAX },
    };

    zero_loss_kernel<<<1, 1>>>();

    // fork aux stream off the capture-origin (default) stream
    cudaEventRecord(ev_fork, 0);
    cudaStreamWaitEvent(s_aux, ev_fork, 0);

    run_scale(ps[0], d_in, 0);       // big scale on main stream
    run_scale(ps[1], d_in, s_aux);   // smaller scales overlap on aux
    run_scale(ps[2], d_in, s_aux);

    // join
    cudaEventRecord(ev_join, s_aux);
    cudaStreamWaitEvent(0, ev_join, 0);

    write_out_kernel<<<1, 1>>>((float*)d_out);
}

// round 8
// speedup vs baseline: 3.9814x; 1.1771x over previous
#include <cuda_runtime.h>
#include <cuda_fp16.h>
#include <cstdint>
#include <math.h>

#define EPS_VAR 1e-9f
#define SMAX (4*1472)

// ---------------- scratch (static device globals; no allocation) ----------------
// Device globals are ONLY referenced from device code (never passed as kernel
// args from host: host would pass the host shadow address, ATS dereferences it).
// Arrays hold all three scales at disjoint offsets so scales can run concurrently.
__device__ float  g_scores[71565312];            // fp32 scores (all scales)
__device__ __half g_Ahi[71565312];               // softmax probs (fp16)
__device__ __half g_Qhi[13631488], g_Qlo[13631488];
__device__ __half g_Khi[13631488], g_Klo[13631488];
__device__ __half g_Whi[13631488];               // [V^T ; (V^2)^T]
__device__ float  g_MT[13631488];                // [M | T] outputs
__device__ float g_sum_q[3*SMAX], g_ss_q[3*SMAX], g_aq[3*SMAX], g_bq[3*SMAX];
__device__ float g_sum_k[3*SMAX], g_ss_k[3*SMAX], g_ak[3*SMAX], g_bk[3*SMAX];
__device__ float g_sum_c[3*SMAX], g_ss_c[3*SMAX], g_ac[3*SMAX], g_bc[3*SMAX];
__device__ double g_loss;

// ---------------- PTX helpers (sm_80-level baseline features only) ----------------
__device__ __forceinline__ uint32_t smem_u32(const void* p){
    uint32_t a; asm("{ .reg .u64 t; cvta.to.shared.u64 t, %1; cvt.u32.u64 %0, t; }" : "=r"(a) : "l"(p)); return a;
}
__device__ __forceinline__ void cp_async16(uint32_t dst, const void* src){
    asm volatile("cp.async.cg.shared.global [%0], [%1], 16;" :: "r"(dst), "l"(src) : "memory");
}
#define CP_COMMIT() asm volatile("cp.async.commit_group;" ::: "memory")
#define CP_WAIT(n)  asm volatile("cp.async.wait_group %0;" :: "n"(n) : "memory")

__device__ __forceinline__ void ldsm4(uint32_t* r, uint32_t addr){
    asm volatile("ldmatrix.sync.aligned.m8n8.x4.shared.b16 {%0,%1,%2,%3}, [%4];"
        : "=r"(r[0]), "=r"(r[1]), "=r"(r[2]), "=r"(r[3]) : "r"(addr));
}
__device__ __forceinline__ void ldsm2(uint32_t* r, uint32_t addr){
    asm volatile("ldmatrix.sync.aligned.m8n8.x2.shared.b16 {%0,%1}, [%2];"
        : "=r"(r[0]), "=r"(r[1]) : "r"(addr));
}
__device__ __forceinline__ void mma_f16(float* c, const uint32_t* a, const uint32_t* b){
    asm volatile("mma.sync.aligned.m16n8k16.row.col.f32.f16.f16.f32 "
        "{%0,%1,%2,%3}, {%4,%5,%6,%7}, {%8,%9}, {%0,%1,%2,%3};"
        : "+f"(c[0]), "+f"(c[1]), "+f"(c[2]), "+f"(c[3])
        : "r"(a[0]), "r"(a[1]), "r"(a[2]), "r"(a[3]), "r"(b[0]), "r"(b[1]));
}

// ---------------- small kernels ----------------
__global__ void zero_loss_kernel() { g_loss = 0.0; }

__global__ void zero_sums_kernel(int soff) {
    int i = blockIdx.x * blockDim.x + threadIdx.x;
    if (i < SMAX) {
        g_sum_q[soff + i] = 0.f; g_ss_q[soff + i] = 0.f;
        g_sum_k[soff + i] = 0.f; g_ss_k[soff + i] = 0.f;
        g_sum_c[soff + i] = 0.f; g_ss_c[soff + i] = 0.f;
    }
}

template<int T>
__global__ void stats_partial_t(const float* __restrict__ x, int N, int C, int rowsPerChunk, int soff) {
    float* gsum = ((T == 0) ? g_sum_q : (T == 1) ? g_sum_k : g_sum_c) + soff;
    float* gss  = ((T == 0) ? g_ss_q  : (T == 1) ? g_ss_k  : g_ss_c) + soff;
    int b = blockIdx.x, chunk = blockIdx.y;
    int r0 = chunk * rowsPerChunk;
    for (int c = threadIdx.x; c < C; c += blockDim.x) {
        float s = 0.f, ss = 0.f;
        const float* p = x + ((size_t)b * N + r0) * C + c;
        for (int r = 0; r < rowsPerChunk; r++) {
            float v = p[(size_t)r * C];
            s += v; ss = fmaf(v, v, ss);
        }
        atomicAdd(&gsum[b * C + c], s);
        atomicAdd(&gss[b * C + c], ss);
    }
}

template<int T>
__global__ void stats_final_t(int N, int C, int B, int soff) {
    const float* gsum = ((T == 0) ? g_sum_q : (T == 1) ? g_sum_k : g_sum_c) + soff;
    const float* gss  = ((T == 0) ? g_ss_q  : (T == 1) ? g_ss_k  : g_ss_c) + soff;
    float* ga = ((T == 0) ? g_aq : (T == 1) ? g_ak : g_ac) + soff;
    float* gb = ((T == 0) ? g_bq : (T == 1) ? g_bk : g_bc) + soff;
    int i = blockIdx.x * blockDim.x + threadIdx.x;
    if (i < B * C) {
        float invN = 1.0f / (float)N;
        float mean = gsum[i] * invN;
        float var  = gss[i] * invN - mean * mean;
        float r = rsqrtf(var + 1e-5f);
        ga[i] = r;
        gb[i] = -mean * r;
    }
}

// normalize + split fp32 -> fp16 hi/lo.  T=0: comb_c -> Q;  T=1: comb_s -> K
template<int T>
__global__ void prep_split_affine(const float* __restrict__ x,
                                  int total, int C, int perBatch, int soff, size_t qoff) {
    const float* ga = ((T == 0) ? g_aq : g_ak) + soff;
    const float* gb = ((T == 0) ? g_bq : g_bk) + soff;
    __half* hi = ((T == 0) ? g_Qhi : g_Khi) + qoff;
    __half* lo = ((T == 0) ? g_Qlo : g_Klo) + qoff;
    int i = blockIdx.x * blockDim.x + threadIdx.x;
    if (i >= total) return;
    int b = i / perBatch;
    int ch = i % C;
    float y = fmaf(x[i], ga[b * C + ch], gb[b * C + ch]);
    __half h = __float2half(y);
    hi[i] = h;
    lo[i] = __float2half(y - __half2float(h));
}

// W = [V^T ; (V^2)^T]  (2C x N per batch), fp16
__global__ void prep_w(const float* __restrict__ v, int N, int C, size_t woff) {
    __shared__ float tile[32][33];
    int b = blockIdx.z;
    int j0 = blockIdx.x * 32, c0 = blockIdx.y * 32;
    int tx = threadIdx.x, ty = threadIdx.y;  // 32 x 8
    const float* vb = v + (size_t)b * N * C;
    #pragma unroll
    for (int r = 0; r < 4; r++)
        tile[ty + 8 * r][tx] = vb[(size_t)(j0 + ty + 8 * r) * C + c0 + tx];
    __syncthreads();
    __half* w = g_Whi + woff + (size_t)b * 2 * C * N;
    #pragma unroll
    for (int r = 0; r < 4; r++) {
        int c = c0 + ty + 8 * r, j = j0 + tx;
        float val = tile[tx][ty + 8 * r];
        w[(size_t)c * N + j] = __float2half(val);
        w[(size_t)(C + c) * N + j] = __float2half(val * val);
    }
}

// ---------------- mma.sync fp16 GEMM: D = X * Y^T ----------------
// MODE 0 (3-term split): X = Qn hi/lo (Kg=Cc), Y = Kn hi/lo, D = scores. 4 tiles/stage.
// MODE 1 (1-term):       X = A fp16 (Kg=N),   Y = W fp16,   D = MT.     2 tiles/stage.
// 128x128 block tile, 8 warps of 64x32, K-chunk 16, cp.async double buffered.
// smem tile: 128 rows x 16 fp16, row stride 48B (ldmatrix conflict-free).
#define KCH 16
#define TROWB 48
#define TILE_BYTES (128 * TROWB)

template<int NT>
__device__ __forceinline__ void load_chunk(uint32_t sbase, const __half* const* srcs,
                                           int Kg, int k0, int tid) {
    int r = tid >> 1, h = tid & 1;          // 256 16B vectors: 128 rows x 2 halves
    #pragma unroll
    for (int a = 0; a < NT; a++)
        cp_async16(sbase + a * TILE_BYTES + r * TROWB + h * 16,
                   srcs[a] + (size_t)r * Kg + k0 + h * 8);
}

template<int MODE>
__global__ __launch_bounds__(256)
void gemm_f16(int Mg, int Ng, int Kg, size_t xoff, size_t yoff, size_t doff) {
    constexpr int NT = (MODE == 0) ? 4 : 2;
    constexpr int STAGE_BYTES = NT * TILE_BYTES;
    extern __shared__ char smem[];
    uint32_t sb = smem_u32(smem);
    int tid = threadIdx.x;
    int wid = tid >> 5, lane = tid & 31;
    int g = lane >> 2, t = lane & 3;
    int warp_m0 = (wid >> 2) << 6;   // 0 or 64
    int warp_n0 = (wid & 3) << 5;    // 0,32,64,96
    int b = blockIdx.z;
    int bi = blockIdx.y * 128, bj = blockIdx.x * 128;

    const __half* Xhi = ((MODE == 0) ? g_Qhi : g_Ahi) + xoff;
    const __half* Xlo = g_Qlo + xoff;                       // MODE 0 only
    const __half* Yhi = ((MODE == 0) ? g_Khi : g_Whi) + yoff;
    const __half* Ylo = g_Klo + yoff;                       // MODE 0 only
    float* D = ((MODE == 0) ? g_scores : g_MT) + doff;

    const __half* xh = Xhi + (size_t)b * Mg * Kg + (size_t)bi * Kg;
    const __half* xl = Xlo + (size_t)b * Mg * Kg + (size_t)bi * Kg;
    const __half* yh = Yhi + (size_t)b * Ng * Kg + (size_t)bj * Kg;
    const __half* yl = Ylo + (size_t)b * Ng * Kg + (size_t)bj * Kg;

    const __half* srcs[NT];
    if (MODE == 0) { srcs[0] = xh; srcs[1] = xl; srcs[2] = yh; srcs[NT - 1] = yl; }
    else           { srcs[0] = xh; srcs[NT - 1] = yh; }

    float acc[4][4][4];
    #pragma unroll
    for (int i = 0; i < 4; i++)
        #pragma unroll
        for (int j = 0; j < 4; j++)
            #pragma unroll
            for (int k = 0; k < 4; k++) acc[i][j][k] = 0.f;

    int nch = Kg / KCH;

    uint32_t a_off = (uint32_t)((warp_m0 + (lane & 15)) * TROWB + (lane >> 4) * 16);
    uint32_t b_off = (uint32_t)((warp_n0 + (lane & 7)) * TROWB + ((lane >> 3) & 1) * 16);

    load_chunk<NT>(sb, srcs, Kg, 0, tid);
    CP_COMMIT();

    for (int i = 0; i < nch; i++) {
        uint32_t stage = (uint32_t)(i & 1) * STAGE_BYTES;
        if (i + 1 < nch) {
            load_chunk<NT>(sb + (uint32_t)((i + 1) & 1) * STAGE_BYTES, srcs, Kg, (i + 1) * KCH, tid);
            CP_COMMIT();
            CP_WAIT(1);
        } else {
            CP_WAIT(0);
        }
        __syncthreads();

        if (MODE == 0) {
            uint32_t sAh = sb + stage;
            uint32_t sAl = sAh + TILE_BYTES;
            uint32_t sBh = sAl + TILE_BYTES;
            uint32_t sBl = sBh + TILE_BYTES;
            uint32_t ah[4][4], al[4][4], bh[4][2], bl[4][2];
            #pragma unroll
            for (int mi = 0; mi < 4; mi++) {
                uint32_t o = a_off + mi * 16 * TROWB;
                ldsm4(ah[mi], sAh + o);
                ldsm4(al[mi], sAl + o);
            }
            #pragma unroll
            for (int ni = 0; ni < 4; ni++) {
                uint32_t o = b_off + ni * 8 * TROWB;
                ldsm2(bh[ni], sBh + o);
                ldsm2(bl[ni], sBl + o);
            }
            #pragma unroll
            for (int mi = 0; mi < 4; mi++)
                #pragma unroll
                for (int ni = 0; ni < 4; ni++) {
                    mma_f16(acc[mi][ni], ah[mi], bh[ni]);
                    mma_f16(acc[mi][ni], ah[mi], bl[ni]);
                    mma_f16(acc[mi][ni], al[mi], bh[ni]);
                }
        } else {
            uint32_t sAh = sb + stage;
            uint32_t sBh = sAh + TILE_BYTES;
            uint32_t ah[4][4], bh[4][2];
            #pragma unroll
            for (int mi = 0; mi < 4; mi++)
                ldsm4(ah[mi], sAh + a_off + mi * 16 * TROWB);
            #pragma unroll
            for (int ni = 0; ni < 4; ni++)
                ldsm2(bh[ni], sBh + b_off + ni * 8 * TROWB);
            #pragma unroll
            for (int mi = 0; mi < 4; mi++)
                #pragma unroll
                for (int ni = 0; ni < 4; ni++)
                    mma_f16(acc[mi][ni], ah[mi], bh[ni]);
        }
        __syncthreads();
    }

    float* db = D + (size_t)b * Mg * Ng;
    #pragma unroll
    for (int mi = 0; mi < 4; mi++) {
        int gr = bi + warp_m0 + mi * 16 + g;
        #pragma unroll
        for (int ni = 0; ni < 4; ni++) {
            int gc = bj + warp_n0 + ni * 8 + t * 2;
            float2 v0 = make_float2(acc[mi][ni][0], acc[mi][ni][1]);
            float2 v1 = make_float2(acc[mi][ni][2], acc[mi][ni][3]);
            *reinterpret_cast<float2*>(db + (size_t)gr * Ng + gc) = v0;
            *reinterpret_cast<float2*>(db + (size_t)(gr + 8) * Ng + gc) = v1;
        }
    }
}

// ---------------- row softmax: fp32 scores -> fp16 probs ----------------
__global__ void softmax_rows(int N, size_t scoff) {
    extern __shared__ float srow[];
    __shared__ float red[33];
    size_t row = blockIdx.x;
    const float* p = g_scores + scoff + row * (size_t)N;
    int tid = threadIdx.x, bd = blockDim.x;

    float m = -1e30f;
    for (int j = tid; j < N; j += bd) {
        float v = p[j];
        srow[j] = v;
        m = fmaxf(m, v);
    }
    #pragma unroll
    for (int o = 16; o > 0; o >>= 1) m = fmaxf(m, __shfl_xor_sync(0xffffffffu, m, o));
    if ((tid & 31) == 0) red[tid >> 5] = m;
    __syncthreads();
    if (tid < 32) {
        float v = (tid < (bd >> 5)) ? red[tid] : -1e30f;
        #pragma unroll
        for (int o = 16; o > 0; o >>= 1) v = fmaxf(v, __shfl_xor_sync(0xffffffffu, v, o));
        if (tid == 0) red[32] = v;
    }
    __syncthreads();
    m = red[32];

    float s = 0.f;
    for (int j = tid; j < N; j += bd) {
        float e = expf(srow[j] - m);
        srow[j] = e;
        s += e;
    }
    __syncthreads();
    #pragma unroll
    for (int o = 16; o > 0; o >>= 1) s += __shfl_xor_sync(0xffffffffu, s, o);
    if ((tid & 31) == 0) red[tid >> 5] = s;
    __syncthreads();
    if (tid < 32) {
        float v = (tid < (bd >> 5)) ? red[tid] : 0.f;
        #pragma unroll
        for (int o = 16; o > 0; o >>= 1) v += __shfl_xor_sync(0xffffffffu, v, o);
        if (tid == 0) red[32] = v;
    }
    __syncthreads();
    float inv = 1.0f / red[32];
    size_t off = scoff + row * (size_t)N;
    for (int j = tid; j < N; j += bd)
        g_Ahi[off + j] = __float2half(srow[j] * inv);
}

// ---------------- loss epilogue from [M|T] ----------------
__global__ void loss_epilogue(const float* __restrict__ cin, const float* __restrict__ cs,
                              int N, int C, float inv_count, int total,
                              size_t mtoff, int soff) {
    int i = blockIdx.x * blockDim.x + threadIdx.x;
    float local = 0.f;
    if (i < total) {
        int c = i % C;
        int r = i / C;          // = b*N + n
        int b = r / N;
        const float* mt = g_MT + mtoff;
        float m = mt[(size_t)r * 2 * C + c];
        float t = mt[(size_t)r * 2 * C + C + c];
        float s2 = t - m * m;
        float s = sqrtf(fmaxf(s2, EPS_VAR));
        float nc = fmaf(cin[i], g_ac[soff + b * C + c], g_bc[soff + b * C + c]);
        float aat = fmaf(s, nc, m);
        float d = cs[i] - aat;
        local = d * d * inv_count;
    }
    #pragma unroll
    for (int o = 16; o > 0; o >>= 1) local += __shfl_xor_sync(0xffffffffu, local, o);
    __shared__ float red[8];
    int tid = threadIdx.x;
    if ((tid & 31) == 0) red[tid >> 5] = local;
    __syncthreads();
    if (tid == 0) {
        float t = 0.f;
        #pragma unroll
        for (int k = 0; k < 8; k++) t += red[k];
        atomicAdd(&g_loss, (double)t);
    }
}

__global__ void write_out_kernel(float* out) { out[0] = (float)g_loss; }

// ---------------- host launcher ----------------
struct ScaleP { int i_cs, i_c, i_s, i_cc, i_sc, N, C, Cc; size_t qoff, woff, scoff; int soff; };

static void run_scale(const ScaleP& p, void* const* d_in, cudaStream_t st) {
    const int B = 4;
    const float* cs = (const float*)d_in[p.i_cs];
    const float* c  = (const float*)d_in[p.i_c];
    const float* stp= (const float*)d_in[p.i_s];
    const float* cc = (const float*)d_in[p.i_cc];
    const float* sc = (const float*)d_in[p.i_sc];

    zero_sums_kernel<<<(SMAX + 255) / 256, 256, 0, st>>>(p.soff);

    dim3 gs(B, p.N / 8);
    stats_partial_t<0><<<gs, 256, 0, st>>>(cc, p.N, p.Cc, 8, p.soff);
    stats_partial_t<1><<<gs, 256, 0, st>>>(sc, p.N, p.Cc, 8, p.soff);
    stats_partial_t<2><<<gs, 256, 0, st>>>(c,  p.N, p.C,  8, p.soff);
    stats_final_t<0><<<(B * p.Cc + 255) / 256, 256, 0, st>>>(p.N, p.Cc, B, p.soff);
    stats_final_t<1><<<(B * p.Cc + 255) / 256, 256, 0, st>>>(p.N, p.Cc, B, p.soff);
    stats_final_t<2><<<(B * p.C  + 255) / 256, 256, 0, st>>>(p.N, p.C,  B, p.soff);

    int totQ = B * p.N * p.Cc;
    prep_split_affine<0><<<(totQ + 255) / 256, 256, 0, st>>>(cc, totQ, p.Cc, p.N * p.Cc, p.soff, p.qoff);
    prep_split_affine<1><<<(totQ + 255) / 256, 256, 0, st>>>(sc, totQ, p.Cc, p.N * p.Cc, p.soff, p.qoff);

    dim3 gw(p.N / 32, p.C / 32, B);
    prep_w<<<gw, dim3(32, 8), 0, st>>>(stp, p.N, p.C, p.woff);

    dim3 g1(p.N / 128, p.N / 128, B);
    gemm_f16<0><<<g1, 256, 2 * 4 * TILE_BYTES, st>>>(p.N, p.N, p.Cc, p.qoff, p.qoff, p.scoff);

    softmax_rows<<<B * p.N, 256, p.N * sizeof(float), st>>>(p.N, p.scoff);

    dim3 g2((2 * p.C) / 128, p.N / 128, B);
    gemm_f16<1><<<g2, 256, 2 * 2 * TILE_BYTES, st>>>(p.N, 2 * p.C, p.N, p.scoff, p.woff, p.woff);

    int tot = B * p.N * p.C;
    float inv_count = 1.0f / (float)tot;
    loss_epilogue<<<(tot + 255) / 256, 256, 0, st>>>(c, cs, p.N, p.C, inv_count, tot, p.woff, p.soff);
}

extern "C" void kernel_launch(void* const* d_in, const int* in_sizes, int n_in,
                              void* d_out, int out_size) {
    (void)in_sizes; (void)n_in; (void)out_size;

    static bool s_init = false;
    static cudaStream_t s_aux;
    static cudaEvent_t ev_fork, ev_join;
    if (!s_init) {
        cudaStreamCreateWithFlags(&s_aux, cudaStreamNonBlocking);
        cudaEventCreateWithFlags(&ev_fork, cudaEventDisableTiming);
        cudaEventCreateWithFlags(&ev_join, cudaEventDisableTiming);
        s_init = true;
    }

    // per-scale buffer offsets (elements)
    ScaleP ps[3] = {
        { 0, 1, 2, 3, 4, 4096, 256,  448, 0,        0,        0,        0      },
        { 5, 6, 7, 8, 9, 1024, 512,  960, 7340032,  8388608,  67108864, SMAX   },
        {10,11,12,13,14, 256, 512, 1472, 11272192, 12582912, 71303168, 2*SMAX },
    };

    zero_loss_kernel<<<1, 1>>>();

    // fork aux stream off the capture-origin (default) stream
    cudaEventRecord(ev_fork, 0);
    cudaStreamWaitEvent(s_aux, ev_fork, 0);

    run_scale(ps[0], d_in, 0);       // big scale on main stream
    run_scale(ps[1], d_in, s_aux);   // smaller scales overlap on aux
    run_scale(ps[2], d_in, s_aux);

    // join
    cudaEventRecord(ev_join, s_aux);
    cudaStreamWaitEvent(0, ev_join, 0);

    write_out_kernel<<<1, 1>>>((float*)d_out);
}

// round 10
// speedup vs baseline: 4.9595x; 1.2457x over previous
#include <cuda_runtime.h>
#include <cuda_fp16.h>
#include <cstdint>
#include <math.h>

#define EPS_VAR 1e-9f
#define SMAX (4*1472)

// ---------------- scratch (static device globals; no allocation) ----------------
// Device globals are ONLY referenced from device code (never passed as kernel
// args from host: host would pass the host shadow address, ATS dereferences it).
// Arrays hold all three scales at disjoint offsets so scales can run concurrently.
__device__ float  g_scores[71565312];            // fp32 scores (all scales)
__device__ __half g_Ahi[71565312];               // softmax probs (fp16)
__device__ __half g_Qhi[13631488], g_Qlo[13631488];
__device__ __half g_Khi[13631488];
__device__ __half g_Whi[13631488];               // [V^T ; (V^2)^T]
__device__ float  g_MT[13631488];                // [M | T] outputs
__device__ float g_sum_q[3*SMAX], g_ss_q[3*SMAX], g_aq[3*SMAX], g_bq[3*SMAX];
__device__ float g_sum_k[3*SMAX], g_ss_k[3*SMAX], g_ak[3*SMAX], g_bk[3*SMAX];
__device__ float g_sum_c[3*SMAX], g_ss_c[3*SMAX], g_ac[3*SMAX], g_bc[3*SMAX];
__device__ double g_loss;

// ---------------- PTX helpers (sm_80-level baseline features only) ----------------
__device__ __forceinline__ uint32_t smem_u32(const void* p){
    uint32_t a; asm("{ .reg .u64 t; cvta.to.shared.u64 t, %1; cvt.u32.u64 %0, t; }" : "=r"(a) : "l"(p)); return a;
}
__device__ __forceinline__ void cp_async16(uint32_t dst, const void* src){
    asm volatile("cp.async.cg.shared.global [%0], [%1], 16;" :: "r"(dst), "l"(src) : "memory");
}
#define CP_COMMIT() asm volatile("cp.async.commit_group;" ::: "memory")
#define CP_WAIT(n)  asm volatile("cp.async.wait_group %0;" :: "n"(n) : "memory")

__device__ __forceinline__ void ldsm4(uint32_t* r, uint32_t addr){
    asm volatile("ldmatrix.sync.aligned.m8n8.x4.shared.b16 {%0,%1,%2,%3}, [%4];"
        : "=r"(r[0]), "=r"(r[1]), "=r"(r[2]), "=r"(r[3]) : "r"(addr));
}
__device__ __forceinline__ void ldsm2(uint32_t* r, uint32_t addr){
    asm volatile("ldmatrix.sync.aligned.m8n8.x2.shared.b16 {%0,%1}, [%2];"
        : "=r"(r[0]), "=r"(r[1]) : "r"(addr));
}
__device__ __forceinline__ void mma_f16(float* c, const uint32_t* a, const uint32_t* b){
    asm volatile("mma.sync.aligned.m16n8k16.row.col.f32.f16.f16.f32 "
        "{%0,%1,%2,%3}, {%4,%5,%6,%7}, {%8,%9}, {%0,%1,%2,%3};"
        : "+f"(c[0]), "+f"(c[1]), "+f"(c[2]), "+f"(c[3])
        : "r"(a[0]), "r"(a[1]), "r"(a[2]), "r"(a[3]), "r"(b[0]), "r"(b[1]));
}

// ---------------- small kernels ----------------
__global__ void zero_loss_kernel() { g_loss = 0.0; }

__global__ void zero_sums_kernel(int soff) {
    int i = blockIdx.x * blockDim.x + threadIdx.x;
    if (i < SMAX) {
        g_sum_q[soff + i] = 0.f; g_ss_q[soff + i] = 0.f;
        g_sum_k[soff + i] = 0.f; g_ss_k[soff + i] = 0.f;
        g_sum_c[soff + i] = 0.f; g_ss_c[soff + i] = 0.f;
    }
}

// merged stats over q (comb_c), k (comb_s), c (content); blockIdx.z selects
__global__ void stats_partial_all(const float* __restrict__ cc, const float* __restrict__ sc,
                                  const float* __restrict__ cv,
                                  int N, int C, int Cc, int soff) {
    int which = blockIdx.z;
    const float* x = (which == 0) ? cc : (which == 1) ? sc : cv;
    int Cx = (which == 2) ? C : Cc;
    float* gsum = ((which == 0) ? g_sum_q : (which == 1) ? g_sum_k : g_sum_c) + soff;
    float* gss  = ((which == 0) ? g_ss_q  : (which == 1) ? g_ss_k  : g_ss_c) + soff;
    int b = blockIdx.x, chunk = blockIdx.y;
    int r0 = chunk * 8;
    for (int c = threadIdx.x; c < Cx; c += blockDim.x) {
        float s = 0.f, ss = 0.f;
        const float* p = x + ((size_t)b * N + r0) * Cx + c;
        #pragma unroll
        for (int r = 0; r < 8; r++) {
            float v = p[(size_t)r * Cx];
            s += v; ss = fmaf(v, v, ss);
        }
        atomicAdd(&gsum[b * Cx + c], s);
        atomicAdd(&gss[b * Cx + c], ss);
    }
}

__global__ void stats_final_all(int N, int C, int Cc, int B, int soff) {
    int which = blockIdx.y;
    int Cx = (which == 2) ? C : Cc;
    const float* gsum = ((which == 0) ? g_sum_q : (which == 1) ? g_sum_k : g_sum_c) + soff;
    const float* gss  = ((which == 0) ? g_ss_q  : (which == 1) ? g_ss_k  : g_ss_c) + soff;
    float* ga = ((which == 0) ? g_aq : (which == 1) ? g_ak : g_ac) + soff;
    float* gb = ((which == 0) ? g_bq : (which == 1) ? g_bk : g_bc) + soff;
    int i = blockIdx.x * blockDim.x + threadIdx.x;
    if (i < B * Cx) {
        float invN = 1.0f / (float)N;
        float mean = gsum[i] * invN;
        float var  = gss[i] * invN - mean * mean;
        float r = rsqrtf(var + 1e-5f);
        ga[i] = r;
        gb[i] = -mean * r;
    }
}

// normalize + split fp32 -> fp16. Q gets hi+lo, K gets hi only (2-term QK).
// blockIdx.y: 0 = comb_c -> Q, 1 = comb_s -> K
__global__ void prep_split_affine(const float* __restrict__ xq, const float* __restrict__ xk,
                                  int total, int C, int perBatch, int soff, size_t qoff) {
    int which = blockIdx.y;
    const float* x  = (which == 0) ? xq : xk;
    const float* ga = ((which == 0) ? g_aq : g_ak) + soff;
    const float* gb = ((which == 0) ? g_bq : g_bk) + soff;
    int i = blockIdx.x * blockDim.x + threadIdx.x;
    if (i >= total) return;
    int b = i / perBatch;
    int ch = i % C;
    float y = fmaf(x[i], ga[b * C + ch], gb[b * C + ch]);
    __half h = __float2half(y);
    if (which == 0) {
        g_Qhi[qoff + i] = h;
        g_Qlo[qoff + i] = __float2half(y - __half2float(h));
    } else {
        g_Khi[qoff + i] = h;
    }
}

// W = [V^T ; (V^2)^T]  (2C x N per batch), fp16
__global__ void prep_w(const float* __restrict__ v, int N, int C, size_t woff) {
    __shared__ float tile[32][33];
    int b = blockIdx.z;
    int j0 = blockIdx.x * 32, c0 = blockIdx.y * 32;
    int tx = threadIdx.x, ty = threadIdx.y;  // 32 x 8
    const float* vb = v + (size_t)b * N * C;
    #pragma unroll
    for (int r = 0; r < 4; r++)
        tile[ty + 8 * r][tx] = vb[(size_t)(j0 + ty + 8 * r) * C + c0 + tx];
    __syncthreads();
    __half* w = g_Whi + woff + (size_t)b * 2 * C * N;
    #pragma unroll
    for (int r = 0; r < 4; r++) {
        int c = c0 + ty + 8 * r, j = j0 + tx;
        float val = tile[tx][ty + 8 * r];
        w[(size_t)c * N + j] = __float2half(val);
        w[(size_t)(C + c) * N + j] = __float2half(val * val);
    }
}

// ---------------- mma.sync fp16 GEMM: D = X * Y^T ----------------
// MODE 0 (2-term): X = Qn hi/lo (Kg=Cc), Y = Kn hi, D = scores.
//                  3 tiles/stage, KCH=16, TROWB=48 -> 2*3*6144 = 36864B smem.
// MODE 1 (1-term): X = A (Kg=N), Y = W, D = MT.
//                  2 tiles/stage, KCH=32, TROWB=80 -> 2*2*10240 = 40960B smem.
// Both fit the 48KB default dynamic-smem limit: NO cudaFuncSetAttribute needed.
// 128x128 block tile, 8 warps of 64x32, cp.async double buffered.
// Bank-conflict check (8-row ldmatrix phase): TROWB=48 -> words 12r mod 32 =
// {0,12,24,4,16,28,8,20}; TROWB=80 -> 20r mod 32 = {0,20,8,28,16,4,24,12}. Both distinct.

template<int MODE>
__global__ __launch_bounds__(256)
void gemm_f16(int Mg, int Ng, int Kg, size_t xoff, size_t yoff, size_t doff) {
    constexpr int NT = (MODE == 0) ? 3 : 2;
    constexpr int KCH = (MODE == 0) ? 16 : 32;
    constexpr int TROWB = (MODE == 0) ? 48 : 80;
    constexpr int TILE_BYTES = 128 * TROWB;
    constexpr int STAGE_BYTES = NT * TILE_BYTES;
    constexpr int NVEC = 128 * KCH / 8;           // 16B vectors per tile
    extern __shared__ char smem[];
    uint32_t sb = smem_u32(smem);
    int tid = threadIdx.x;
    int wid = tid >> 5, lane = tid & 31;
    int g = lane >> 2, t = lane & 3;
    int warp_m0 = (wid >> 2) << 6;   // 0 or 64
    int warp_n0 = (wid & 3) << 5;    // 0,32,64,96
    int b = blockIdx.z;
    int bi = blockIdx.y * 128, bj = blockIdx.x * 128;

    const __half* Xhi = ((MODE == 0) ? g_Qhi : g_Ahi) + xoff;
    const __half* Xlo = g_Qlo + xoff;                       // MODE 0 only
    const __half* Yhi = ((MODE == 0) ? g_Khi : g_Whi) + yoff;
    float* D = ((MODE == 0) ? g_scores : g_MT) + doff;

    const __half* srcs[NT];
    srcs[0] = Xhi + (size_t)b * Mg * Kg + (size_t)bi * Kg;
    if (MODE == 0) {
        srcs[1] = Xlo + (size_t)b * Mg * Kg + (size_t)bi * Kg;
    }
    srcs[NT - 1] = Yhi + (size_t)b * Ng * Kg + (size_t)bj * Kg;

    float acc[4][4][4];
    #pragma unroll
    for (int i = 0; i < 4; i++)
        #pragma unroll
        for (int j = 0; j < 4; j++)
            #pragma unroll
            for (int k = 0; k < 4; k++) acc[i][j][k] = 0.f;

    int nch = Kg / KCH;

    uint32_t a_off = (uint32_t)((warp_m0 + (lane & 15)) * TROWB + (lane >> 4) * 16);
    uint32_t b_off = (uint32_t)((warp_n0 + (lane & 7)) * TROWB + ((lane >> 3) & 1) * 16);

    // loader lambda: NVEC 16B vectors per tile, 256 threads
    auto load_chunk = [&](uint32_t sbase, int k0) {
        constexpr int HPR = KCH / 8;          // 16B halves per row
        #pragma unroll
        for (int a = 0; a < NT; a++) {
            #pragma unroll
            for (int v = 0; v < NVEC / 256; v++) {
                int idx = tid + v * 256;
                int r = idx / HPR, h = idx % HPR;
                cp_async16(sbase + a * TILE_BYTES + r * TROWB + h * 16,
                           srcs[a] + (size_t)r * Kg + k0 + h * 8);
            }
        }
    };

    load_chunk(sb, 0);
    CP_COMMIT();

    for (int i = 0; i < nch; i++) {
        uint32_t stage = (uint32_t)(i & 1) * STAGE_BYTES;
        if (i + 1 < nch) {
            load_chunk(sb + (uint32_t)((i + 1) & 1) * STAGE_BYTES, (i + 1) * KCH);
            CP_COMMIT();
            CP_WAIT(1);
        } else {
            CP_WAIT(0);
        }
        __syncthreads();

        #pragma unroll
        for (int ks = 0; ks < KCH / 16; ks++) {
            uint32_t kso = (uint32_t)(ks * 32);
            if (MODE == 0) {
                uint32_t sAh = sb + stage;
                uint32_t sAl = sAh + TILE_BYTES;
                uint32_t sBh = sAl + TILE_BYTES;
                uint32_t ah[4][4], al[4][4], bh[4][2];
                #pragma unroll
                for (int mi = 0; mi < 4; mi++) {
                    uint32_t o = a_off + kso + mi * 16 * TROWB;
                    ldsm4(ah[mi], sAh + o);
                    ldsm4(al[mi], sAl + o);
                }
                #pragma unroll
                for (int ni = 0; ni < 4; ni++)
                    ldsm2(bh[ni], sBh + b_off + kso + ni * 8 * TROWB);
                #pragma unroll
                for (int mi = 0; mi < 4; mi++)
                    #pragma unroll
                    for (int ni = 0; ni < 4; ni++) {
                        mma_f16(acc[mi][ni], ah[mi], bh[ni]);
                        mma_f16(acc[mi][ni], al[mi], bh[ni]);
                    }
            } else {
                uint32_t sAh = sb + stage;
                uint32_t sBh = sAh + TILE_BYTES;
                uint32_t ah[4][4], bh[4][2];
                #pragma unroll
                for (int mi = 0; mi < 4; mi++)
                    ldsm4(ah[mi], sAh + a_off + kso + mi * 16 * TROWB);
                #pragma unroll
                for (int ni = 0; ni < 4; ni++)
                    ldsm2(bh[ni], sBh + b_off + kso + ni * 8 * TROWB);
                #pragma unroll
                for (int mi = 0; mi < 4; mi++)
                    #pragma unroll
                    for (int ni = 0; ni < 4; ni++)
                        mma_f16(acc[mi][ni], ah[mi], bh[ni]);
            }
        }
        __syncthreads();
    }

    float* db = D + (size_t)b * Mg * Ng;
    #pragma unroll
    for (int mi = 0; mi < 4; mi++) {
        int gr = bi + warp_m0 + mi * 16 + g;
        #pragma unroll
        for (int ni = 0; ni < 4; ni++) {
            int gc = bj + warp_n0 + ni * 8 + t * 2;
            float2 v0 = make_float2(acc[mi][ni][0], acc[mi][ni][1]);
            float2 v1 = make_float2(acc[mi][ni][2], acc[mi][ni][3]);
            *reinterpret_cast<float2*>(db + (size_t)gr * Ng + gc) = v0;
            *reinterpret_cast<float2*>(db + (size_t)(gr + 8) * Ng + gc) = v1;
        }
    }
}

// ---------------- row softmax: fp32 scores -> fp16 probs ----------------
__global__ void softmax_rows(int N, size_t scoff) {
    extern __shared__ float srow[];
    __shared__ float red[33];
    size_t row = blockIdx.x;
    const float* p = g_scores + scoff + row * (size_t)N;
    int tid = threadIdx.x, bd = blockDim.x;

    float m = -1e30f;
    for (int j = tid; j < N; j += bd) {
        float v = p[j];
        srow[j] = v;
        m = fmaxf(m, v);
    }
    #pragma unroll
    for (int o = 16; o > 0; o >>= 1) m = fmaxf(m, __shfl_xor_sync(0xffffffffu, m, o));
    if ((tid & 31) == 0) red[tid >> 5] = m;
    __syncthreads();
    if (tid < 32) {
        float v = (tid < (bd >> 5)) ? red[tid] : -1e30f;
        #pragma unroll
        for (int o = 16; o > 0; o >>= 1) v = fmaxf(v, __shfl_xor_sync(0xffffffffu, v, o));
        if (tid == 0) red[32] = v;
    }
    __syncthreads();
    m = red[32];

    float s = 0.f;
    for (int j = tid; j < N; j += bd) {
        float e = expf(srow[j] - m);
        srow[j] = e;
        s += e;
    }
    __syncthreads();
    #pragma unroll
    for (int o = 16; o > 0; o >>= 1) s += __shfl_xor_sync(0xffffffffu, s, o);
    if ((tid & 31) == 0) red[tid >> 5] = s;
    __syncthreads();
    if (tid < 32) {
        float v = (tid < (bd >> 5)) ? red[tid] : 0.f;
        #pragma unroll
        for (int o = 16; o > 0; o >>= 1) v += __shfl_xor_sync(0xffffffffu, v, o);
        if (tid == 0) red[32] = v;
    }
    __syncthreads();
    float inv = 1.0f / red[32];
    size_t off = scoff + row * (size_t)N;
    for (int j = tid; j < N; j += bd)
        g_Ahi[off + j] = __float2half(srow[j] * inv);
}

// ---------------- loss epilogue from [M|T] ----------------
__global__ void loss_epilogue(const float* __restrict__ cin, const float* __restrict__ cs,
                              int N, int C, float inv_count, int total,
                              size_t mtoff, int soff) {
    int i = blockIdx.x * blockDim.x + threadIdx.x;
    float local = 0.f;
    if (i < total) {
        int c = i % C;
        int r = i / C;          // = b*N + n
        int b = r / N;
        const float* mt = g_MT + mtoff;
        float m = mt[(size_t)r * 2 * C + c];
        float t = mt[(size_t)r * 2 * C + C + c];
        float s2 = t - m * m;
        float s = sqrtf(fmaxf(s2, EPS_VAR));
        float nc = fmaf(cin[i], g_ac[soff + b * C + c], g_bc[soff + b * C + c]);
        float aat = fmaf(s, nc, m);
        float d = cs[i] - aat;
        local = d * d * inv_count;
    }
    #pragma unroll
    for (int o = 16; o > 0; o >>= 1) local += __shfl_xor_sync(0xffffffffu, local, o);
    __shared__ float red[8];
    int tid = threadIdx.x;
    if ((tid & 31) == 0) red[tid >> 5] = local;
    __syncthreads();
    if (tid == 0) {
        float t = 0.f;
        #pragma unroll
        for (int k = 0; k < 8; k++) t += red[k];
        atomicAdd(&g_loss, (double)t);
    }
}

__global__ void write_out_kernel(float* out) { out[0] = (float)g_loss; }

// ---------------- host launcher ----------------
struct ScaleP { int i_cs, i_c, i_s, i_cc, i_sc, N, C, Cc; size_t qoff, woff, scoff; int soff; };

static void run_scale(const ScaleP& p, void* const* d_in, cudaStream_t st) {
    const int B = 4;
    const float* cs = (const float*)d_in[p.i_cs];
    const float* c  = (const float*)d_in[p.i_c];
    const float* stp= (const float*)d_in[p.i_s];
    const float* cc = (const float*)d_in[p.i_cc];
    const float* sc = (const float*)d_in[p.i_sc];

    zero_sums_kernel<<<(SMAX + 255) / 256, 256, 0, st>>>(p.soff);

    dim3 gs(B, p.N / 8, 3);
    stats_partial_all<<<gs, 256, 0, st>>>(cc, sc, c, p.N, p.C, p.Cc, p.soff);
    dim3 gf((B * p.Cc + 255) / 256, 3);
    stats_final_all<<<gf, 256, 0, st>>>(p.N, p.C, p.Cc, B, p.soff);

    int totQ = B * p.N * p.Cc;
    dim3 gp((totQ + 255) / 256, 2);
    prep_split_affine<<<gp, 256, 0, st>>>(cc, sc, totQ, p.Cc, p.N * p.Cc, p.soff, p.qoff);

    dim3 gw(p.N / 32, p.C / 32, B);
    prep_w<<<gw, dim3(32, 8), 0, st>>>(stp, p.N, p.C, p.woff);

    dim3 g1(p.N / 128, p.N / 128, B);
    gemm_f16<0><<<g1, 256, 2 * 3 * 128 * 48, st>>>(p.N, p.N, p.Cc, p.qoff, p.qoff, p.scoff);

    softmax_rows<<<B * p.N, 256, p.N * sizeof(float), st>>>(p.N, p.scoff);

    dim3 g2((2 * p.C) / 128, p.N / 128, B);
    gemm_f16<1><<<g2, 256, 2 * 2 * 128 * 80, st>>>(p.N, 2 * p.C, p.N, p.scoff, p.woff, p.woff);

    int tot = B * p.N * p.C;
    float inv_count = 1.0f / (float)tot;
    loss_epilogue<<<(tot + 255) / 256, 256, 0, st>>>(c, cs, p.N, p.C, inv_count, tot, p.woff, p.soff);
}

extern "C" void kernel_launch(void* const* d_in, const int* in_sizes, int n_in,
                              void* d_out, int out_size) {
    (void)in_sizes; (void)n_in; (void)out_size;

    static bool s_init = false;
    static cudaStream_t s_aux;
    static cudaEvent_t ev_fork, ev_join;
    if (!s_init) {
        cudaStreamCreateWithFlags(&s_aux, cudaStreamNonBlocking);
        cudaEventCreateWithFlags(&ev_fork, cudaEventDisableTiming);
        cudaEventCreateWithFlags(&ev_join, cudaEventDisableTiming);
        s_init = true;
    }

    // per-scale buffer offsets (elements)
    ScaleP ps[3] = {
        { 0, 1, 2, 3, 4, 4096, 256,  448, 0,        0,        0,        0      },
        { 5, 6, 7, 8, 9, 1024, 512,  960, 7340032,  8388608,  67108864, SMAX   },
        {10,11,12,13,14, 256, 512, 1472, 11272192, 12582912, 71303168, 2*SMAX },
    };

    zero_loss_kernel<<<1, 1>>>();

    // fork aux stream off the capture-origin (default) stream
    cudaEventRecord(ev_fork, 0);
    cudaStreamWaitEvent(s_aux, ev_fork, 0);

    run_scale(ps[0], d_in, 0);       // big scale on main stream
    run_scale(ps[1], d_in, s_aux);   // smaller scales overlap on aux
    run_scale(ps[2], d_in, s_aux);

    // join
    cudaEventRecord(ev_join, s_aux);
    cudaStreamWaitEvent(0, ev_join, 0);

    write_out_kernel<<<1, 1>>>((float*)d_out);
}